// round 11
// baseline (speedup 1.0000x reference)
#include <cuda_runtime.h>
#include <cuda_bf16.h>
#include <math.h>

// Problem constants (fixed by the dataset)
#define NN 100000           // nodes
#define EE 1600000          // edges
#define KIN 256             // in_feats
#define HD  128             // H*D
#define NHEAD 4
#define DDIM 32
#define NEG_SLOPE 0.2f

#define NB_SCAN 98          // ceil(NN/1024)

// ---------------- device scratch (static, no allocations) ----------------
__device__ float g_ft[(size_t)NN * HD];    // projected features [N,128]
__device__ float g_res[(size_t)NN * HD];   // residual projection [N,128]
__device__ float g_el[NN * NHEAD];
__device__ float g_er[NN * NHEAD];
__device__ int   g_deg[NN];
__device__ int   g_rowptr[NN];
__device__ int   g_fill[NN];
__device__ int   g_esrc[EE];
__device__ int   g_bsum[NB_SCAN + 1];
__device__ int   g_idx32;                  // 1 if src/dst are int32, 0 if int64

// ---------------- helpers ----------------
__device__ __forceinline__ int load_idx(const void* p, int i, int is32) {
    if (is32) return ((const int*)p)[i];
    return (int)(((const long long*)p)[i]);
}

// ---------------- K0: zero state ----------------
__global__ void zero_kernel() {
    int i = blockIdx.x * blockDim.x + threadIdx.x;
    int stride = gridDim.x * blockDim.x;
    for (int j = i; j < NN; j += stride) g_deg[j] = 0;
    if (i == 0) g_idx32 = 0;
}

// ---------------- K1: detect index dtype ----------------
// Interpret buffers as u64 words. int64 node ids (< 100000) always have zero
// high words; int32 data read as u64 packs two ids per word -> high word is
// the odd-position id, which is nonzero with overwhelming probability over
// 800k samples.
__global__ void detect_kernel(const unsigned long long* __restrict__ s,
                              const unsigned long long* __restrict__ d,
                              int nwords) {
    int i = blockIdx.x * blockDim.x + threadIdx.x;
    int stride = gridDim.x * blockDim.x;
    int found = 0;
    for (int j = i; j < nwords; j += stride) {
        if ((s[j] >> 32) | (d[j] >> 32)) { found = 1; break; }
    }
    if (found) g_idx32 = 1;
}

// ---------------- K2: fused dual SGEMM ----------------
// C[N,256] = feat[N,256] @ Wcat^T, Wcat = [fc_w ; res_w] (each [128,256]).
// blockIdx.y==0 -> ft, ==1 -> res. Classic 128x128x8 register-blocked SGEMM.
#define BM 128
#define BN 128
#define BK 8
#define TM 8
#define TN 8
#define PAD 4

__global__ __launch_bounds__(256, 2)
void gemm_kernel(const float* __restrict__ feat,
                 const float* __restrict__ fc_w,
                 const float* __restrict__ res_w) {
    __shared__ float As[BK][BM + PAD];
    __shared__ float Bs[BK][BN + PAD];

    const int block_m = blockIdx.x * BM;
    const float* __restrict__ W = (blockIdx.y == 0) ? fc_w : res_w;   // [128,256]
    float* __restrict__ C = (blockIdx.y == 0) ? g_ft : g_res;

    const int tid = threadIdx.x;
    const int tx = tid & 15;          // 16 col-groups
    const int ty = tid >> 4;          // 16 row-groups
    const int row0 = ty * TM;
    const int col0 = tx * TN;

    // A tile load mapping: 128x8 = 1024 floats, 4 per thread (float4 along k)
    const int a_m = tid >> 1;
    const int a_k = (tid & 1) * 4;
    // B tile: Bs[k][n] = W[n][k]; 8x128, 4 per thread
    const int b_n = tid >> 1;
    const int b_k = (tid & 1) * 4;

    float acc[TM][TN];
#pragma unroll
    for (int i = 0; i < TM; i++)
#pragma unroll
        for (int j = 0; j < TN; j++) acc[i][j] = 0.f;

    const int gm_a = block_m + a_m;
    const bool a_ok = (gm_a < NN);
    const float* a_base = feat + (size_t)gm_a * KIN + a_k;
    const float* b_base = W + (size_t)b_n * KIN + b_k;

    for (int kk = 0; kk < KIN; kk += BK) {
        float4 av = a_ok ? *reinterpret_cast<const float4*>(a_base + kk)
                         : make_float4(0.f, 0.f, 0.f, 0.f);
        float4 bv = *reinterpret_cast<const float4*>(b_base + kk);

        As[a_k + 0][a_m] = av.x; As[a_k + 1][a_m] = av.y;
        As[a_k + 2][a_m] = av.z; As[a_k + 3][a_m] = av.w;
        Bs[b_k + 0][b_n] = bv.x; Bs[b_k + 1][b_n] = bv.y;
        Bs[b_k + 2][b_n] = bv.z; Bs[b_k + 3][b_n] = bv.w;
        __syncthreads();

#pragma unroll
        for (int k = 0; k < BK; k++) {
            float ar[TM], br[TN];
#pragma unroll
            for (int i = 0; i < TM; i++) ar[i] = As[k][row0 + i];
#pragma unroll
            for (int j = 0; j < TN; j++) br[j] = Bs[k][col0 + j];
#pragma unroll
            for (int i = 0; i < TM; i++)
#pragma unroll
                for (int j = 0; j < TN; j++)
                    acc[i][j] = fmaf(ar[i], br[j], acc[i][j]);
        }
        __syncthreads();
    }

#pragma unroll
    for (int i = 0; i < TM; i++) {
        int gm = block_m + row0 + i;
        if (gm < NN) {
            float* crow = C + (size_t)gm * HD + col0;
            *reinterpret_cast<float4*>(crow) =
                make_float4(acc[i][0], acc[i][1], acc[i][2], acc[i][3]);
            *reinterpret_cast<float4*>(crow + 4) =
                make_float4(acc[i][4], acc[i][5], acc[i][6], acc[i][7]);
        }
    }
}

// ---------------- K3: per-node attention logits el/er ----------------
// One block of 128 threads per node; each warp = one head (lane = d).
__global__ void logits_kernel(const float* __restrict__ attn_l,
                              const float* __restrict__ attn_r) {
    int n = blockIdx.x;
    int t = threadIdx.x;           // 0..127
    int h = t >> 5;
    int d = t & 31;
    float v = g_ft[(size_t)n * HD + t];
    float pl = v * attn_l[t];
    float pr = v * attn_r[t];
#pragma unroll
    for (int o = 16; o > 0; o >>= 1) {
        pl += __shfl_down_sync(0xffffffffu, pl, o);
        pr += __shfl_down_sync(0xffffffffu, pr, o);
    }
    if (d == 0) {
        g_el[n * NHEAD + h] = pl;
        g_er[n * NHEAD + h] = pr;
    }
}

// ---------------- K4: degree histogram ----------------
__global__ void hist_kernel(const void* __restrict__ dst) {
    int is32 = g_idx32;
    int i = blockIdx.x * blockDim.x + threadIdx.x;
    int stride = gridDim.x * blockDim.x;
    for (int e = i; e < EE; e += stride) {
        int d = load_idx(dst, e, is32);
        atomicAdd(&g_deg[d], 1);
    }
}

// ---------------- K5a: per-block sums for scan ----------------
__global__ void block_sums_kernel() {
    __shared__ int sh[32];
    int i = blockIdx.x * 1024 + threadIdx.x;
    int v = (i < NN) ? g_deg[i] : 0;
#pragma unroll
    for (int o = 16; o > 0; o >>= 1) v += __shfl_down_sync(0xffffffffu, v, o);
    if ((threadIdx.x & 31) == 0) sh[threadIdx.x >> 5] = v;
    __syncthreads();
    if (threadIdx.x < 32) {
        int w = sh[threadIdx.x];
#pragma unroll
        for (int o = 16; o > 0; o >>= 1) w += __shfl_down_sync(0xffffffffu, w, o);
        if (threadIdx.x == 0) g_bsum[blockIdx.x] = w;
    }
}

// ---------------- K5b: exclusive scan of block sums (tiny) ----------------
__global__ void scan_sums_kernel() {
    if (threadIdx.x == 0 && blockIdx.x == 0) {
        int running = 0;
        for (int b = 0; b < NB_SCAN; b++) {
            int t = g_bsum[b];
            g_bsum[b] = running;
            running += t;
        }
    }
}

// ---------------- K5c: per-block exclusive scan + offset ----------------
__global__ void scan_final_kernel() {
    __shared__ int sh[1024];
    int i = blockIdx.x * 1024 + threadIdx.x;
    int tid = threadIdx.x;
    int v = (i < NN) ? g_deg[i] : 0;
    int x = v;
    sh[tid] = x;
    __syncthreads();
#pragma unroll
    for (int off = 1; off < 1024; off <<= 1) {
        int y = (tid >= off) ? sh[tid - off] : 0;
        __syncthreads();
        x += y;
        sh[tid] = x;
        __syncthreads();
    }
    if (i < NN) {
        int excl = x - v + g_bsum[blockIdx.x];
        g_rowptr[i] = excl;
        g_fill[i] = excl;
    }
}

// ---------------- K6: scatter edges into CSR (by dst) ----------------
__global__ void scatter_kernel(const void* __restrict__ src,
                               const void* __restrict__ dst) {
    int is32 = g_idx32;
    int i = blockIdx.x * blockDim.x + threadIdx.x;
    int stride = gridDim.x * blockDim.x;
    for (int e = i; e < EE; e += stride) {
        int d = load_idx(dst, e, is32);
        int s = load_idx(src, e, is32);
        int pos = atomicAdd(&g_fill[d], 1);
        g_esrc[pos] = s;
    }
}

// ---------------- K7: fused edge-softmax + aggregation + residual ----------
// One warp per (node, head); lane = feature d. Denominator folded into the
// same loop: agg = sum(ex*ft[src]) / sum(ex). No atomics, no alpha storage.
__global__ __launch_bounds__(256)
void agg_kernel(float* __restrict__ out, int out_size) {
    int gwarp = (blockIdx.x * blockDim.x + threadIdx.x) >> 5;
    int lane = threadIdx.x & 31;
    if (gwarp >= NN * NHEAD) return;
    int n = gwarp >> 2;
    int h = gwarp & 3;

    int start = g_rowptr[n];
    int len = g_deg[n];
    float ernh = g_er[n * NHEAD + h];

    const float* __restrict__ ftp = g_ft + (size_t)h * DDIM + lane;
    float acc = 0.f, sume = 0.f;
    for (int i = 0; i < len; i++) {
        int s = g_esrc[start + i];
        float e = g_el[s * NHEAD + h] + ernh;
        e = (e > 0.f) ? e : NEG_SLOPE * e;
        float ex = expf(e);
        sume += ex;
        acc = fmaf(ex, ftp[(size_t)s * HD], acc);
    }
    float a = (len > 0) ? (acc / sume) : 0.f;

    size_t o = (size_t)n * HD + h * DDIM + lane;
    float r = g_res[o];
    out[o] = a + r;                                   // rst
    if (out_size >= 2 * NN * HD)
        out[(size_t)NN * HD + o] = a;                 // agg (dglrst)
}

// ---------------- launch ----------------
extern "C" void kernel_launch(void* const* d_in, const int* in_sizes, int n_in,
                              void* d_out, int out_size) {
    const float* feat   = (const float*)d_in[0];
    const void*  src    = d_in[1];
    const void*  dst    = d_in[2];
    const float* fc_w   = (const float*)d_in[3];
    const float* attn_l = (const float*)d_in[4];
    const float* attn_r = (const float*)d_in[5];
    const float* res_w  = (const float*)d_in[6];
    float* out = (float*)d_out;

    zero_kernel<<<256, 256>>>();
    detect_kernel<<<256, 256>>>((const unsigned long long*)src,
                                (const unsigned long long*)dst, EE / 2);

    dim3 ggrid((NN + BM - 1) / BM, 2);
    gemm_kernel<<<ggrid, 256>>>(feat, fc_w, res_w);

    logits_kernel<<<NN, 128>>>(attn_l, attn_r);

    hist_kernel<<<512, 256>>>(dst);
    block_sums_kernel<<<NB_SCAN, 1024>>>();
    scan_sums_kernel<<<1, 32>>>();
    scan_final_kernel<<<NB_SCAN, 1024>>>();
    scatter_kernel<<<512, 256>>>(src, dst);

    int total_warps = NN * NHEAD;                      // 400000
    int blocks = (total_warps * 32 + 255) / 256;       // 50000
    agg_kernel<<<blocks, 256>>>(out, out_size);
}

// round 13
// speedup vs baseline: 1.3369x; 1.3369x over previous
#include <cuda_runtime.h>
#include <cuda_bf16.h>
#include <stdint.h>
#include <math.h>

// Problem constants (fixed by the dataset)
#define NN 100000           // nodes
#define EE 1600000          // edges
#define KIN 256             // in_feats
#define HD  128             // H*D
#define NHEAD 4
#define DDIM 32
#define NEG_SLOPE 0.2f

#define NB_SCAN 98          // ceil(NN/1024)

// ---------------- device scratch (static, no allocations) ----------------
__device__ float g_ft[(size_t)NN * HD];    // projected features [N,128]
__device__ float g_res[(size_t)NN * HD];   // residual projection [N,128]
__device__ float g_el[NN * NHEAD];
__device__ float g_er[NN * NHEAD];
__device__ int   g_deg[NN];
__device__ int   g_rowptr[NN];
__device__ int   g_fill[NN];
__device__ int   g_esrc[EE];
__device__ int   g_bsum[NB_SCAN + 1];
__device__ int   g_idx32;                  // 1 if src/dst are int32, 0 if int64

// ---------------- helpers ----------------
__device__ __forceinline__ int load_idx(const void* p, int i, int is32) {
    if (is32) return ((const int*)p)[i];
    return (int)(((const long long*)p)[i]);
}

__device__ __forceinline__ uint32_t smem_u32(const void* p) {
    uint32_t a;
    asm("{ .reg .u64 t; cvta.to.shared.u64 t, %1; cvt.u32.u64 %0, t; }"
        : "=r"(a) : "l"(p));
    return a;
}

__device__ __forceinline__ void ldsm_x4(uint32_t* r, uint32_t addr) {
    asm volatile("ldmatrix.sync.aligned.m8n8.x4.shared.b16 {%0,%1,%2,%3}, [%4];"
                 : "=r"(r[0]), "=r"(r[1]), "=r"(r[2]), "=r"(r[3]) : "r"(addr));
}

__device__ __forceinline__ void mma_bf16(float* d, const uint32_t* a,
                                         const uint32_t* b) {
    asm volatile(
        "mma.sync.aligned.m16n8k16.row.col.f32.bf16.bf16.f32 "
        "{%0,%1,%2,%3}, {%4,%5,%6,%7}, {%8,%9}, {%0,%1,%2,%3};\n"
        : "+f"(d[0]), "+f"(d[1]), "+f"(d[2]), "+f"(d[3])
        : "r"(a[0]), "r"(a[1]), "r"(a[2]), "r"(a[3]), "r"(b[0]), "r"(b[1]));
}

// split fp32 pair -> packed bf16x2 hi / lo
__device__ __forceinline__ void split_pack(float v0, float v1,
                                           uint32_t& hi, uint32_t& lo) {
    __nv_bfloat16 h0 = __float2bfloat16_rn(v0);
    __nv_bfloat16 h1 = __float2bfloat16_rn(v1);
    __nv_bfloat16 l0 = __float2bfloat16_rn(v0 - __bfloat162float(h0));
    __nv_bfloat16 l1 = __float2bfloat16_rn(v1 - __bfloat162float(h1));
    hi = ((uint32_t)__bfloat16_as_ushort(h1) << 16) | __bfloat16_as_ushort(h0);
    lo = ((uint32_t)__bfloat16_as_ushort(l1) << 16) | __bfloat16_as_ushort(l0);
}

// ---------------- K0: zero state ----------------
__global__ void zero_kernel() {
    int i = blockIdx.x * blockDim.x + threadIdx.x;
    int stride = gridDim.x * blockDim.x;
    for (int j = i; j < NN; j += stride) g_deg[j] = 0;
    if (i == 0) g_idx32 = 0;
}

// ---------------- K1: detect index dtype ----------------
__global__ void detect_kernel(const unsigned long long* __restrict__ s,
                              const unsigned long long* __restrict__ d,
                              int nwords) {
    int i = blockIdx.x * blockDim.x + threadIdx.x;
    int stride = gridDim.x * blockDim.x;
    int found = 0;
    for (int j = i; j < nwords; j += stride) {
        if ((s[j] >> 32) | (d[j] >> 32)) { found = 1; break; }
    }
    if (found) g_idx32 = 1;
}

// ---------------- K2: split-bf16 HMMA GEMM (+ fused el/er epilogue) -------
// C[128-tile,128] = feat[128,256] @ W^T using mma.sync m16n8k16 bf16.
// blockIdx.y == 0 -> ft (also computes el/er), == 1 -> res.
// CTA: 256 threads = 8 warps; warp grid 4(m) x 2(n); warp tile 32x64.
#define AST 40   // smem row stride in bf16 elements (80B, conflict-free ldmatrix)

__global__ __launch_bounds__(256, 1)
void gemm_mma_kernel(const float* __restrict__ feat,
                     const float* __restrict__ fc_w,
                     const float* __restrict__ res_w,
                     const float* __restrict__ attn_l,
                     const float* __restrict__ attn_r) {
    __shared__ __align__(16) __nv_bfloat16 sAh[128 * AST];
    __shared__ __align__(16) __nv_bfloat16 sAl[128 * AST];
    __shared__ __align__(16) __nv_bfloat16 sBh[128 * AST];
    __shared__ __align__(16) __nv_bfloat16 sBl[128 * AST];
    __shared__ float s_attn[2 * HD];

    const int tid = threadIdx.x;
    const int wid = tid >> 5;
    const int lane = tid & 31;
    const int wm = wid & 3;          // m-warp: rows wm*32..+31
    const int wn = wid >> 2;         // n-warp: cols wn*64..+63
    const int isft = (blockIdx.y == 0);
    const int block_m = blockIdx.x * 128;
    const float* __restrict__ W = isft ? fc_w : res_w;
    float* __restrict__ C = isft ? g_ft : g_res;

    if (isft && tid < 128) {
        s_attn[tid] = attn_l[tid];
        s_attn[HD + tid] = attn_r[tid];
    }

    // ---- load mapping: thread pair per row; 16 consecutive k-floats ----
    const int arow = tid >> 1;               // 0..127
    const int acol0 = (tid & 1) * 16;        // 0 or 16
    const int gm = block_m + arow;
    const bool a_ok = (gm < NN);
    const float* __restrict__ Abase = feat + (size_t)(a_ok ? gm : 0) * KIN + acol0;
    const float* __restrict__ Bbase = W + (size_t)arow * KIN + acol0;

    float4 pa[4], pb[4];
#pragma unroll
    for (int j = 0; j < 4; j++) {
        pa[j] = a_ok ? *reinterpret_cast<const float4*>(Abase + j * 4)
                     : make_float4(0.f, 0.f, 0.f, 0.f);
        pb[j] = *reinterpret_cast<const float4*>(Bbase + j * 4);
    }

    float acc[2][8][4];
#pragma unroll
    for (int mb = 0; mb < 2; mb++)
#pragma unroll
        for (int nb = 0; nb < 8; nb++)
#pragma unroll
            for (int c = 0; c < 4; c++) acc[mb][nb][c] = 0.f;

    const uint32_t sAh_b = smem_u32(sAh), sAl_b = smem_u32(sAl);
    const uint32_t sBh_b = smem_u32(sBh), sBl_b = smem_u32(sBl);
    // ldmatrix lane-address components
    const int a_row_l = (lane & 15);
    const int a_chunk = (lane >> 4);               // 0/1 -> k-halves
    const int b_kchunk = (lane >> 3) & 1;
    const int b_nhalf = (lane >> 4) & 1;           // which n8 of the pair
    const int b_row_l = (lane & 7);

#pragma unroll 1
    for (int kk = 0; kk < KIN; kk += 32) {
        // ---- convert prefetched regs -> smem (hi/lo split) ----
        {
            uint32_t h[8], l[8];
            split_pack(pa[0].x, pa[0].y, h[0], l[0]);
            split_pack(pa[0].z, pa[0].w, h[1], l[1]);
            split_pack(pa[1].x, pa[1].y, h[2], l[2]);
            split_pack(pa[1].z, pa[1].w, h[3], l[3]);
            split_pack(pa[2].x, pa[2].y, h[4], l[4]);
            split_pack(pa[2].z, pa[2].w, h[5], l[5]);
            split_pack(pa[3].x, pa[3].y, h[6], l[6]);
            split_pack(pa[3].z, pa[3].w, h[7], l[7]);
            uint4* ph = reinterpret_cast<uint4*>(&sAh[arow * AST + acol0]);
            uint4* pl = reinterpret_cast<uint4*>(&sAl[arow * AST + acol0]);
            ph[0] = make_uint4(h[0], h[1], h[2], h[3]);
            ph[1] = make_uint4(h[4], h[5], h[6], h[7]);
            pl[0] = make_uint4(l[0], l[1], l[2], l[3]);
            pl[1] = make_uint4(l[4], l[5], l[6], l[7]);

            split_pack(pb[0].x, pb[0].y, h[0], l[0]);
            split_pack(pb[0].z, pb[0].w, h[1], l[1]);
            split_pack(pb[1].x, pb[1].y, h[2], l[2]);
            split_pack(pb[1].z, pb[1].w, h[3], l[3]);
            split_pack(pb[2].x, pb[2].y, h[4], l[4]);
            split_pack(pb[2].z, pb[2].w, h[5], l[5]);
            split_pack(pb[3].x, pb[3].y, h[6], l[6]);
            split_pack(pb[3].z, pb[3].w, h[7], l[7]);
            uint4* qh = reinterpret_cast<uint4*>(&sBh[arow * AST + acol0]);
            uint4* ql = reinterpret_cast<uint4*>(&sBl[arow * AST + acol0]);
            qh[0] = make_uint4(h[0], h[1], h[2], h[3]);
            qh[1] = make_uint4(h[4], h[5], h[6], h[7]);
            ql[0] = make_uint4(l[0], l[1], l[2], l[3]);
            ql[1] = make_uint4(l[4], l[5], l[6], l[7]);
        }
        __syncthreads();

        // ---- prefetch next chunk (overlaps with MMA below) ----
        if (kk + 32 < KIN) {
#pragma unroll
            for (int j = 0; j < 4; j++) {
                pa[j] = a_ok ? *reinterpret_cast<const float4*>(Abase + kk + 32 + j * 4)
                             : make_float4(0.f, 0.f, 0.f, 0.f);
                pb[j] = *reinterpret_cast<const float4*>(Bbase + kk + 32 + j * 4);
            }
        }

        // ---- MMA over the two k16 steps of this chunk ----
#pragma unroll
        for (int k16 = 0; k16 < 32; k16 += 16) {
            uint32_t ah[2][4], al[2][4], bh[8][2], bl[8][2];
#pragma unroll
            for (int mb = 0; mb < 2; mb++) {
                uint32_t off = (uint32_t)(((wm * 32 + mb * 16 + a_row_l) * AST +
                                           k16 + a_chunk * 8) * 2);
                ldsm_x4(ah[mb], sAh_b + off);
                ldsm_x4(al[mb], sAl_b + off);
            }
#pragma unroll
            for (int j = 0; j < 4; j++) {
                int nrow = wn * 64 + (2 * j + b_nhalf) * 8 + b_row_l;
                uint32_t off = (uint32_t)((nrow * AST + k16 + b_kchunk * 8) * 2);
                uint32_t t[4];
                ldsm_x4(t, sBh_b + off);
                bh[2 * j][0] = t[0]; bh[2 * j][1] = t[1];
                bh[2 * j + 1][0] = t[2]; bh[2 * j + 1][1] = t[3];
                ldsm_x4(t, sBl_b + off);
                bl[2 * j][0] = t[0]; bl[2 * j][1] = t[1];
                bl[2 * j + 1][0] = t[2]; bl[2 * j + 1][1] = t[3];
            }
#pragma unroll
            for (int mb = 0; mb < 2; mb++)
#pragma unroll
                for (int nb = 0; nb < 8; nb++) {
                    mma_bf16(acc[mb][nb], ah[mb], bh[nb]);
                    mma_bf16(acc[mb][nb], al[mb], bh[nb]);
                    mma_bf16(acc[mb][nb], ah[mb], bl[nb]);
                }
        }
        __syncthreads();
    }

    // ---- epilogue: store C + fused el/er (quad-shuffle reduction) ----
    const int qrow = lane >> 2;      // 0..7
    const int qcol = lane & 3;       // 0..3
#pragma unroll
    for (int mb = 0; mb < 2; mb++) {
        int r0 = block_m + wm * 32 + mb * 16 + qrow;
#pragma unroll
        for (int nb = 0; nb < 8; nb++) {
            int col = wn * 64 + nb * 8 + qcol * 2;
            if (r0 < NN)
                *reinterpret_cast<float2*>(C + (size_t)r0 * HD + col) =
                    make_float2(acc[mb][nb][0], acc[mb][nb][1]);
            if (r0 + 8 < NN)
                *reinterpret_cast<float2*>(C + (size_t)(r0 + 8) * HD + col) =
                    make_float2(acc[mb][nb][2], acc[mb][nb][3]);
        }
        if (isft) {
#pragma unroll
            for (int rr = 0; rr < 2; rr++) {
                int row = r0 + rr * 8;
#pragma unroll
                for (int hh = 0; hh < 2; hh++) {
                    float el = 0.f, er = 0.f;
#pragma unroll
                    for (int nb4 = 0; nb4 < 4; nb4++) {
                        int nb = hh * 4 + nb4;
                        int col = wn * 64 + nb * 8 + qcol * 2;
                        float v0 = acc[mb][nb][rr * 2];
                        float v1 = acc[mb][nb][rr * 2 + 1];
                        el = fmaf(v0, s_attn[col], el);
                        el = fmaf(v1, s_attn[col + 1], el);
                        er = fmaf(v0, s_attn[HD + col], er);
                        er = fmaf(v1, s_attn[HD + col + 1], er);
                    }
                    el += __shfl_xor_sync(0xffffffffu, el, 1);
                    el += __shfl_xor_sync(0xffffffffu, el, 2);
                    er += __shfl_xor_sync(0xffffffffu, er, 1);
                    er += __shfl_xor_sync(0xffffffffu, er, 2);
                    if (qcol == 0 && row < NN) {
                        int head = wn * 2 + hh;
                        g_el[row * NHEAD + head] = el;
                        g_er[row * NHEAD + head] = er;
                    }
                }
            }
        }
    }
}

// ---------------- K4: degree histogram ----------------
__global__ void hist_kernel(const void* __restrict__ dst) {
    int is32 = g_idx32;
    int i = blockIdx.x * blockDim.x + threadIdx.x;
    int stride = gridDim.x * blockDim.x;
    for (int e = i; e < EE; e += stride) {
        int d = load_idx(dst, e, is32);
        atomicAdd(&g_deg[d], 1);
    }
}

// ---------------- K5a: per-block sums for scan ----------------
__global__ void block_sums_kernel() {
    __shared__ int sh[32];
    int i = blockIdx.x * 1024 + threadIdx.x;
    int v = (i < NN) ? g_deg[i] : 0;
#pragma unroll
    for (int o = 16; o > 0; o >>= 1) v += __shfl_down_sync(0xffffffffu, v, o);
    if ((threadIdx.x & 31) == 0) sh[threadIdx.x >> 5] = v;
    __syncthreads();
    if (threadIdx.x < 32) {
        int w = sh[threadIdx.x];
#pragma unroll
        for (int o = 16; o > 0; o >>= 1) w += __shfl_down_sync(0xffffffffu, w, o);
        if (threadIdx.x == 0) g_bsum[blockIdx.x] = w;
    }
}

// ---------------- K5b: exclusive scan of block sums (tiny) ----------------
__global__ void scan_sums_kernel() {
    if (threadIdx.x == 0 && blockIdx.x == 0) {
        int running = 0;
        for (int b = 0; b < NB_SCAN; b++) {
            int t = g_bsum[b];
            g_bsum[b] = running;
            running += t;
        }
    }
}

// ---------------- K5c: per-block exclusive scan + offset ----------------
__global__ void scan_final_kernel() {
    __shared__ int sh[1024];
    int i = blockIdx.x * 1024 + threadIdx.x;
    int tid = threadIdx.x;
    int v = (i < NN) ? g_deg[i] : 0;
    int x = v;
    sh[tid] = x;
    __syncthreads();
#pragma unroll
    for (int off = 1; off < 1024; off <<= 1) {
        int y = (tid >= off) ? sh[tid - off] : 0;
        __syncthreads();
        x += y;
        sh[tid] = x;
        __syncthreads();
    }
    if (i < NN) {
        int excl = x - v + g_bsum[blockIdx.x];
        g_rowptr[i] = excl;
        g_fill[i] = excl;
    }
}

// ---------------- K6: scatter edges into CSR (by dst) ----------------
__global__ void scatter_kernel(const void* __restrict__ src,
                               const void* __restrict__ dst) {
    int is32 = g_idx32;
    int i = blockIdx.x * blockDim.x + threadIdx.x;
    int stride = gridDim.x * blockDim.x;
    for (int e = i; e < EE; e += stride) {
        int d = load_idx(dst, e, is32);
        int s = load_idx(src, e, is32);
        int pos = atomicAdd(&g_fill[d], 1);
        g_esrc[pos] = s;
    }
}

// ---------------- K7: fused edge-softmax + aggregation + residual ----------
__global__ __launch_bounds__(256)
void agg_kernel(float* __restrict__ out, int out_size) {
    int gwarp = (blockIdx.x * blockDim.x + threadIdx.x) >> 5;
    int lane = threadIdx.x & 31;
    if (gwarp >= NN * NHEAD) return;
    int n = gwarp >> 2;
    int h = gwarp & 3;

    int start = g_rowptr[n];
    int len = g_deg[n];
    float ernh = g_er[n * NHEAD + h];

    const float* __restrict__ ftp = g_ft + (size_t)h * DDIM + lane;
    float acc = 0.f, sume = 0.f;
    int s_next = (len > 0) ? g_esrc[start] : 0;
    for (int i = 0; i < len; i++) {
        int s = s_next;
        if (i + 1 < len) s_next = g_esrc[start + i + 1];
        float e = g_el[s * NHEAD + h] + ernh;
        e = (e > 0.f) ? e : NEG_SLOPE * e;
        float ex = expf(e);
        sume += ex;
        acc = fmaf(ex, ftp[(size_t)s * HD], acc);
    }
    float a = (len > 0) ? (acc / sume) : 0.f;

    size_t o = (size_t)n * HD + h * DDIM + lane;
    float r = g_res[o];
    out[o] = a + r;                                   // rst
    if (out_size >= 2 * NN * HD)
        out[(size_t)NN * HD + o] = a;                 // agg (dglrst)
}

// ---------------- launch ----------------
extern "C" void kernel_launch(void* const* d_in, const int* in_sizes, int n_in,
                              void* d_out, int out_size) {
    const float* feat   = (const float*)d_in[0];
    const void*  src    = d_in[1];
    const void*  dst    = d_in[2];
    const float* fc_w   = (const float*)d_in[3];
    const float* attn_l = (const float*)d_in[4];
    const float* attn_r = (const float*)d_in[5];
    const float* res_w  = (const float*)d_in[6];
    float* out = (float*)d_out;

    zero_kernel<<<256, 256>>>();
    detect_kernel<<<256, 256>>>((const unsigned long long*)src,
                                (const unsigned long long*)dst, EE / 2);

    dim3 ggrid((NN + 127) / 128, 2);
    gemm_mma_kernel<<<ggrid, 256>>>(feat, fc_w, res_w, attn_l, attn_r);

    hist_kernel<<<512, 256>>>(dst);
    block_sums_kernel<<<NB_SCAN, 1024>>>();
    scan_sums_kernel<<<1, 32>>>();
    scan_final_kernel<<<NB_SCAN, 1024>>>();
    scatter_kernel<<<512, 256>>>(src, dst);

    int total_warps = NN * NHEAD;                      // 400000
    int blocks = (total_warps * 32 + 255) / 256;       // 50000
    agg_kernel<<<blocks, 256>>>(out, out_size);
}

// round 14
// speedup vs baseline: 1.3549x; 1.0135x over previous
#include <cuda_runtime.h>
#include <cuda_bf16.h>
#include <stdint.h>
#include <math.h>

// Problem constants (fixed by the dataset)
#define NN 100000           // nodes
#define EE 1600000          // edges
#define KIN 256             // in_feats
#define HD  128             // H*D
#define NHEAD 4
#define DDIM 32
#define NEG_SLOPE 0.2f

#define NB_SCAN 98          // ceil(NN/1024)

// ---------------- device scratch (static, no allocations) ----------------
__device__ float g_ft[(size_t)NN * HD];    // projected features [N,128]
__device__ float g_res[(size_t)NN * HD];   // residual projection [N,128]
__device__ float g_el[NN * NHEAD];
__device__ float g_er[NN * NHEAD];
__device__ int   g_deg[NN];
__device__ int   g_rowptr[NN];
__device__ int   g_fill[NN];
__device__ int   g_esrc[EE];
__device__ int   g_bsum[NB_SCAN + 1];
__device__ int   g_idx32;                  // 1 if src/dst are int32, 0 if int64

// ---------------- helpers ----------------
__device__ __forceinline__ int load_idx(const void* p, int i, int is32) {
    if (is32) return ((const int*)p)[i];
    return (int)(((const long long*)p)[i]);
}

__device__ __forceinline__ uint32_t smem_u32(const void* p) {
    uint32_t a;
    asm("{ .reg .u64 t; cvta.to.shared.u64 t, %1; cvt.u32.u64 %0, t; }"
        : "=r"(a) : "l"(p));
    return a;
}

__device__ __forceinline__ void ldsm_x4(uint32_t* r, uint32_t addr) {
    asm volatile("ldmatrix.sync.aligned.m8n8.x4.shared.b16 {%0,%1,%2,%3}, [%4];"
                 : "=r"(r[0]), "=r"(r[1]), "=r"(r[2]), "=r"(r[3]) : "r"(addr));
}

__device__ __forceinline__ void mma_bf16(float* d, const uint32_t* a,
                                         const uint32_t* b) {
    asm volatile(
        "mma.sync.aligned.m16n8k16.row.col.f32.bf16.bf16.f32 "
        "{%0,%1,%2,%3}, {%4,%5,%6,%7}, {%8,%9}, {%0,%1,%2,%3};\n"
        : "+f"(d[0]), "+f"(d[1]), "+f"(d[2]), "+f"(d[3])
        : "r"(a[0]), "r"(a[1]), "r"(a[2]), "r"(a[3]), "r"(b[0]), "r"(b[1]));
}

// split fp32 pair -> packed bf16x2 hi / lo
__device__ __forceinline__ void split_pack(float v0, float v1,
                                           uint32_t& hi, uint32_t& lo) {
    __nv_bfloat16 h0 = __float2bfloat16_rn(v0);
    __nv_bfloat16 h1 = __float2bfloat16_rn(v1);
    __nv_bfloat16 l0 = __float2bfloat16_rn(v0 - __bfloat162float(h0));
    __nv_bfloat16 l1 = __float2bfloat16_rn(v1 - __bfloat162float(h1));
    hi = ((uint32_t)__bfloat16_as_ushort(h1) << 16) | __bfloat16_as_ushort(h0);
    lo = ((uint32_t)__bfloat16_as_ushort(l1) << 16) | __bfloat16_as_ushort(l0);
}

// ---------------- K0: zero state ----------------
__global__ void zero_kernel() {
    int i = blockIdx.x * blockDim.x + threadIdx.x;
    int stride = gridDim.x * blockDim.x;
    for (int j = i; j < NN; j += stride) g_deg[j] = 0;
    if (i == 0) g_idx32 = 0;
}

// ---------------- K1: detect index dtype ----------------
__global__ void detect_kernel(const unsigned long long* __restrict__ s,
                              const unsigned long long* __restrict__ d,
                              int nwords) {
    int i = blockIdx.x * blockDim.x + threadIdx.x;
    int stride = gridDim.x * blockDim.x;
    int found = 0;
    for (int j = i; j < nwords; j += stride) {
        if ((s[j] >> 32) | (d[j] >> 32)) { found = 1; break; }
    }
    if (found) g_idx32 = 1;
}

// ---------------- K2: split-bf16 HMMA GEMM (+ fused el/er epilogue) -------
// C[128-tile,128] = feat[128,256] @ W^T using mma.sync m16n8k16 bf16.
// blockIdx.y == 0 -> ft (also computes el/er), == 1 -> res.
// CTA: 256 threads = 8 warps; warp grid 4(m) x 2(n); warp tile 32x64.
#define AST 40   // smem row stride in bf16 elements (80B, conflict-free ldmatrix)

__global__ __launch_bounds__(256, 1)
void gemm_mma_kernel(const float* __restrict__ feat,
                     const float* __restrict__ fc_w,
                     const float* __restrict__ res_w,
                     const float* __restrict__ attn_l,
                     const float* __restrict__ attn_r) {
    __shared__ __align__(16) __nv_bfloat16 sAh[128 * AST];
    __shared__ __align__(16) __nv_bfloat16 sAl[128 * AST];
    __shared__ __align__(16) __nv_bfloat16 sBh[128 * AST];
    __shared__ __align__(16) __nv_bfloat16 sBl[128 * AST];
    __shared__ float s_attn[2 * HD];

    const int tid = threadIdx.x;
    const int wid = tid >> 5;
    const int lane = tid & 31;
    const int wm = wid & 3;          // m-warp: rows wm*32..+31
    const int wn = wid >> 2;         // n-warp: cols wn*64..+63
    const int isft = (blockIdx.y == 0);
    const int block_m = blockIdx.x * 128;
    const float* __restrict__ W = isft ? fc_w : res_w;
    float* __restrict__ C = isft ? g_ft : g_res;

    if (isft && tid < 128) {
        s_attn[tid] = attn_l[tid];
        s_attn[HD + tid] = attn_r[tid];
    }

    // ---- load mapping: thread pair per row; 16 consecutive k-floats ----
    const int arow = tid >> 1;               // 0..127
    const int acol0 = (tid & 1) * 16;        // 0 or 16
    const int gm = block_m + arow;
    const bool a_ok = (gm < NN);
    const float* __restrict__ Abase = feat + (size_t)(a_ok ? gm : 0) * KIN + acol0;
    const float* __restrict__ Bbase = W + (size_t)arow * KIN + acol0;

    float4 pa[4], pb[4];
#pragma unroll
    for (int j = 0; j < 4; j++) {
        pa[j] = a_ok ? *reinterpret_cast<const float4*>(Abase + j * 4)
                     : make_float4(0.f, 0.f, 0.f, 0.f);
        pb[j] = *reinterpret_cast<const float4*>(Bbase + j * 4);
    }

    float acc[2][8][4];
#pragma unroll
    for (int mb = 0; mb < 2; mb++)
#pragma unroll
        for (int nb = 0; nb < 8; nb++)
#pragma unroll
            for (int c = 0; c < 4; c++) acc[mb][nb][c] = 0.f;

    const uint32_t sAh_b = smem_u32(sAh), sAl_b = smem_u32(sAl);
    const uint32_t sBh_b = smem_u32(sBh), sBl_b = smem_u32(sBl);
    // ldmatrix lane-address components
    const int a_row_l = (lane & 15);
    const int a_chunk = (lane >> 4);               // 0/1 -> k-halves
    const int b_kchunk = (lane >> 3) & 1;
    const int b_nhalf = (lane >> 4) & 1;           // which n8 of the pair
    const int b_row_l = (lane & 7);

#pragma unroll 1
    for (int kk = 0; kk < KIN; kk += 32) {
        // ---- convert prefetched regs -> smem (hi/lo split) ----
        {
            uint32_t h[8], l[8];
            split_pack(pa[0].x, pa[0].y, h[0], l[0]);
            split_pack(pa[0].z, pa[0].w, h[1], l[1]);
            split_pack(pa[1].x, pa[1].y, h[2], l[2]);
            split_pack(pa[1].z, pa[1].w, h[3], l[3]);
            split_pack(pa[2].x, pa[2].y, h[4], l[4]);
            split_pack(pa[2].z, pa[2].w, h[5], l[5]);
            split_pack(pa[3].x, pa[3].y, h[6], l[6]);
            split_pack(pa[3].z, pa[3].w, h[7], l[7]);
            uint4* ph = reinterpret_cast<uint4*>(&sAh[arow * AST + acol0]);
            uint4* pl = reinterpret_cast<uint4*>(&sAl[arow * AST + acol0]);
            ph[0] = make_uint4(h[0], h[1], h[2], h[3]);
            ph[1] = make_uint4(h[4], h[5], h[6], h[7]);
            pl[0] = make_uint4(l[0], l[1], l[2], l[3]);
            pl[1] = make_uint4(l[4], l[5], l[6], l[7]);

            split_pack(pb[0].x, pb[0].y, h[0], l[0]);
            split_pack(pb[0].z, pb[0].w, h[1], l[1]);
            split_pack(pb[1].x, pb[1].y, h[2], l[2]);
            split_pack(pb[1].z, pb[1].w, h[3], l[3]);
            split_pack(pb[2].x, pb[2].y, h[4], l[4]);
            split_pack(pb[2].z, pb[2].w, h[5], l[5]);
            split_pack(pb[3].x, pb[3].y, h[6], l[6]);
            split_pack(pb[3].z, pb[3].w, h[7], l[7]);
            uint4* qh = reinterpret_cast<uint4*>(&sBh[arow * AST + acol0]);
            uint4* ql = reinterpret_cast<uint4*>(&sBl[arow * AST + acol0]);
            qh[0] = make_uint4(h[0], h[1], h[2], h[3]);
            qh[1] = make_uint4(h[4], h[5], h[6], h[7]);
            ql[0] = make_uint4(l[0], l[1], l[2], l[3]);
            ql[1] = make_uint4(l[4], l[5], l[6], l[7]);
        }
        __syncthreads();

        // ---- prefetch next chunk (overlaps with MMA below) ----
        if (kk + 32 < KIN) {
#pragma unroll
            for (int j = 0; j < 4; j++) {
                pa[j] = a_ok ? *reinterpret_cast<const float4*>(Abase + kk + 32 + j * 4)
                             : make_float4(0.f, 0.f, 0.f, 0.f);
                pb[j] = *reinterpret_cast<const float4*>(Bbase + kk + 32 + j * 4);
            }
        }

        // ---- MMA over the two k16 steps of this chunk ----
#pragma unroll
        for (int k16 = 0; k16 < 32; k16 += 16) {
            uint32_t ah[2][4], al[2][4], bh[8][2], bl[8][2];
#pragma unroll
            for (int mb = 0; mb < 2; mb++) {
                uint32_t off = (uint32_t)(((wm * 32 + mb * 16 + a_row_l) * AST +
                                           k16 + a_chunk * 8) * 2);
                ldsm_x4(ah[mb], sAh_b + off);
                ldsm_x4(al[mb], sAl_b + off);
            }
#pragma unroll
            for (int j = 0; j < 4; j++) {
                int nrow = wn * 64 + (2 * j + b_nhalf) * 8 + b_row_l;
                uint32_t off = (uint32_t)((nrow * AST + k16 + b_kchunk * 8) * 2);
                uint32_t t[4];
                ldsm_x4(t, sBh_b + off);
                bh[2 * j][0] = t[0]; bh[2 * j][1] = t[1];
                bh[2 * j + 1][0] = t[2]; bh[2 * j + 1][1] = t[3];
                ldsm_x4(t, sBl_b + off);
                bl[2 * j][0] = t[0]; bl[2 * j][1] = t[1];
                bl[2 * j + 1][0] = t[2]; bl[2 * j + 1][1] = t[3];
            }
#pragma unroll
            for (int mb = 0; mb < 2; mb++)
#pragma unroll
                for (int nb = 0; nb < 8; nb++) {
                    mma_bf16(acc[mb][nb], ah[mb], bh[nb]);
                    mma_bf16(acc[mb][nb], al[mb], bh[nb]);
                    mma_bf16(acc[mb][nb], ah[mb], bl[nb]);
                }
        }
        __syncthreads();
    }

    // ---- epilogue: store C + fused el/er (quad-shuffle reduction) ----
    const int qrow = lane >> 2;      // 0..7
    const int qcol = lane & 3;       // 0..3
#pragma unroll
    for (int mb = 0; mb < 2; mb++) {
        int r0 = block_m + wm * 32 + mb * 16 + qrow;
#pragma unroll
        for (int nb = 0; nb < 8; nb++) {
            int col = wn * 64 + nb * 8 + qcol * 2;
            if (r0 < NN)
                *reinterpret_cast<float2*>(C + (size_t)r0 * HD + col) =
                    make_float2(acc[mb][nb][0], acc[mb][nb][1]);
            if (r0 + 8 < NN)
                *reinterpret_cast<float2*>(C + (size_t)(r0 + 8) * HD + col) =
                    make_float2(acc[mb][nb][2], acc[mb][nb][3]);
        }
        if (isft) {
#pragma unroll
            for (int rr = 0; rr < 2; rr++) {
                int row = r0 + rr * 8;
#pragma unroll
                for (int hh = 0; hh < 2; hh++) {
                    float el = 0.f, er = 0.f;
#pragma unroll
                    for (int nb4 = 0; nb4 < 4; nb4++) {
                        int nb = hh * 4 + nb4;
                        int col = wn * 64 + nb * 8 + qcol * 2;
                        float v0 = acc[mb][nb][rr * 2];
                        float v1 = acc[mb][nb][rr * 2 + 1];
                        el = fmaf(v0, s_attn[col], el);
                        el = fmaf(v1, s_attn[col + 1], el);
                        er = fmaf(v0, s_attn[HD + col], er);
                        er = fmaf(v1, s_attn[HD + col + 1], er);
                    }
                    el += __shfl_xor_sync(0xffffffffu, el, 1);
                    el += __shfl_xor_sync(0xffffffffu, el, 2);
                    er += __shfl_xor_sync(0xffffffffu, er, 1);
                    er += __shfl_xor_sync(0xffffffffu, er, 2);
                    if (qcol == 0 && row < NN) {
                        int head = wn * 2 + hh;
                        g_el[row * NHEAD + head] = el;
                        g_er[row * NHEAD + head] = er;
                    }
                }
            }
        }
    }
}

// ---------------- K4: degree histogram ----------------
__global__ void hist_kernel(const void* __restrict__ dst) {
    int is32 = g_idx32;
    int i = blockIdx.x * blockDim.x + threadIdx.x;
    int stride = gridDim.x * blockDim.x;
    for (int e = i; e < EE; e += stride) {
        int d = load_idx(dst, e, is32);
        atomicAdd(&g_deg[d], 1);
    }
}

// ---------------- K5a: per-block sums for scan ----------------
__global__ void block_sums_kernel() {
    __shared__ int sh[32];
    int i = blockIdx.x * 1024 + threadIdx.x;
    int v = (i < NN) ? g_deg[i] : 0;
#pragma unroll
    for (int o = 16; o > 0; o >>= 1) v += __shfl_down_sync(0xffffffffu, v, o);
    if ((threadIdx.x & 31) == 0) sh[threadIdx.x >> 5] = v;
    __syncthreads();
    if (threadIdx.x < 32) {
        int w = sh[threadIdx.x];
#pragma unroll
        for (int o = 16; o > 0; o >>= 1) w += __shfl_down_sync(0xffffffffu, w, o);
        if (threadIdx.x == 0) g_bsum[blockIdx.x] = w;
    }
}

// ---------------- K5b: exclusive scan of block sums (tiny) ----------------
__global__ void scan_sums_kernel() {
    if (threadIdx.x == 0 && blockIdx.x == 0) {
        int running = 0;
        for (int b = 0; b < NB_SCAN; b++) {
            int t = g_bsum[b];
            g_bsum[b] = running;
            running += t;
        }
    }
}

// ---------------- K5c: per-block exclusive scan + offset ----------------
__global__ void scan_final_kernel() {
    __shared__ int sh[1024];
    int i = blockIdx.x * 1024 + threadIdx.x;
    int tid = threadIdx.x;
    int v = (i < NN) ? g_deg[i] : 0;
    int x = v;
    sh[tid] = x;
    __syncthreads();
#pragma unroll
    for (int off = 1; off < 1024; off <<= 1) {
        int y = (tid >= off) ? sh[tid - off] : 0;
        __syncthreads();
        x += y;
        sh[tid] = x;
        __syncthreads();
    }
    if (i < NN) {
        int excl = x - v + g_bsum[blockIdx.x];
        g_rowptr[i] = excl;
        g_fill[i] = excl;
    }
}

// ---------------- K6: scatter edges into CSR (by dst) ----------------
__global__ void scatter_kernel(const void* __restrict__ src,
                               const void* __restrict__ dst) {
    int is32 = g_idx32;
    int i = blockIdx.x * blockDim.x + threadIdx.x;
    int stride = gridDim.x * blockDim.x;
    for (int e = i; e < EE; e += stride) {
        int d = load_idx(dst, e, is32);
        int s = load_idx(src, e, is32);
        int pos = atomicAdd(&g_fill[d], 1);
        g_esrc[pos] = s;
    }
}

// ---------------- K7: fused edge-softmax + aggregation + residual ----------
__global__ __launch_bounds__(256)
void agg_kernel(float* __restrict__ out, int out_size) {
    int gwarp = (blockIdx.x * blockDim.x + threadIdx.x) >> 5;
    int lane = threadIdx.x & 31;
    if (gwarp >= NN * NHEAD) return;
    int n = gwarp >> 2;
    int h = gwarp & 3;

    int start = g_rowptr[n];
    int len = g_deg[n];
    float ernh = g_er[n * NHEAD + h];

    const float* __restrict__ ftp = g_ft + (size_t)h * DDIM + lane;
    float acc = 0.f, sume = 0.f;
    int s_next = (len > 0) ? g_esrc[start] : 0;
    for (int i = 0; i < len; i++) {
        int s = s_next;
        if (i + 1 < len) s_next = g_esrc[start + i + 1];
        float e = g_el[s * NHEAD + h] + ernh;
        e = (e > 0.f) ? e : NEG_SLOPE * e;
        float ex = expf(e);
        sume += ex;
        acc = fmaf(ex, ftp[(size_t)s * HD], acc);
    }
    float a = (len > 0) ? (acc / sume) : 0.f;

    size_t o = (size_t)n * HD + h * DDIM + lane;
    float r = g_res[o];
    out[o] = a + r;                                   // rst
    if (out_size >= 2 * NN * HD)
        out[(size_t)NN * HD + o] = a;                 // agg (dglrst)
}

// ---------------- launch ----------------
extern "C" void kernel_launch(void* const* d_in, const int* in_sizes, int n_in,
                              void* d_out, int out_size) {
    const float* feat   = (const float*)d_in[0];
    const void*  src    = d_in[1];
    const void*  dst    = d_in[2];
    const float* fc_w   = (const float*)d_in[3];
    const float* attn_l = (const float*)d_in[4];
    const float* attn_r = (const float*)d_in[5];
    const float* res_w  = (const float*)d_in[6];
    float* out = (float*)d_out;

    zero_kernel<<<256, 256>>>();
    detect_kernel<<<256, 256>>>((const unsigned long long*)src,
                                (const unsigned long long*)dst, EE / 2);

    dim3 ggrid((NN + 127) / 128, 2);
    gemm_mma_kernel<<<ggrid, 256>>>(feat, fc_w, res_w, attn_l, attn_r);

    hist_kernel<<<512, 256>>>(dst);
    block_sums_kernel<<<NB_SCAN, 1024>>>();
    scan_sums_kernel<<<1, 32>>>();
    scan_final_kernel<<<NB_SCAN, 1024>>>();
    scatter_kernel<<<512, 256>>>(src, dst);

    int total_warps = NN * NHEAD;                      // 400000
    int blocks = (total_warps * 32 + 255) / 256;       // 50000
    agg_kernel<<<blocks, 256>>>(out, out_size);
}

// round 15
// speedup vs baseline: 1.3643x; 1.0069x over previous
#include <cuda_runtime.h>
#include <cuda_bf16.h>
#include <stdint.h>
#include <math.h>

// Problem constants (fixed by the dataset)
#define NN 100000           // nodes
#define EE 1600000          // edges
#define KIN 256             // in_feats
#define HD  128             // H*D
#define NHEAD 4
#define DDIM 32
#define NEG_SLOPE 0.2f

#define NB_SCAN 98          // ceil(NN/1024)

// ---------------- device scratch (static, no allocations) ----------------
__device__ float g_ft[(size_t)NN * HD];    // projected features [N,128]
__device__ float g_res[(size_t)NN * HD];   // residual projection [N,128]
__device__ float g_el[NN * NHEAD];
__device__ float g_er[NN * NHEAD];
__device__ int   g_deg[NN];
__device__ int   g_rowptr[NN];
__device__ int   g_fill[NN];
__device__ int   g_esrc[EE];
__device__ int   g_bsum[NB_SCAN + 1];
__device__ int   g_idx32;                  // 1 if src/dst are int32, 0 if int64

// ---------------- helpers ----------------
__device__ __forceinline__ int load_idx(const void* p, int i, int is32) {
    if (is32) return ((const int*)p)[i];
    return (int)(((const long long*)p)[i]);
}

__device__ __forceinline__ uint32_t smem_u32(const void* p) {
    uint32_t a;
    asm("{ .reg .u64 t; cvta.to.shared.u64 t, %1; cvt.u32.u64 %0, t; }"
        : "=r"(a) : "l"(p));
    return a;
}

__device__ __forceinline__ void ldsm_x4(uint32_t* r, uint32_t addr) {
    asm volatile("ldmatrix.sync.aligned.m8n8.x4.shared.b16 {%0,%1,%2,%3}, [%4];"
                 : "=r"(r[0]), "=r"(r[1]), "=r"(r[2]), "=r"(r[3]) : "r"(addr));
}

__device__ __forceinline__ void mma_bf16(float* d, const uint32_t* a,
                                         const uint32_t* b) {
    asm volatile(
        "mma.sync.aligned.m16n8k16.row.col.f32.bf16.bf16.f32 "
        "{%0,%1,%2,%3}, {%4,%5,%6,%7}, {%8,%9}, {%0,%1,%2,%3};\n"
        : "+f"(d[0]), "+f"(d[1]), "+f"(d[2]), "+f"(d[3])
        : "r"(a[0]), "r"(a[1]), "r"(a[2]), "r"(a[3]), "r"(b[0]), "r"(b[1]));
}

// split fp32 pair -> packed bf16x2 hi / lo
__device__ __forceinline__ void split_pack(float v0, float v1,
                                           uint32_t& hi, uint32_t& lo) {
    __nv_bfloat16 h0 = __float2bfloat16_rn(v0);
    __nv_bfloat16 h1 = __float2bfloat16_rn(v1);
    __nv_bfloat16 l0 = __float2bfloat16_rn(v0 - __bfloat162float(h0));
    __nv_bfloat16 l1 = __float2bfloat16_rn(v1 - __bfloat162float(h1));
    hi = ((uint32_t)__bfloat16_as_ushort(h1) << 16) | __bfloat16_as_ushort(h0);
    lo = ((uint32_t)__bfloat16_as_ushort(l1) << 16) | __bfloat16_as_ushort(l0);
}

// ---------------- K0: zero state ----------------
__global__ void zero_kernel() {
    int i = blockIdx.x * blockDim.x + threadIdx.x;
    int stride = gridDim.x * blockDim.x;
    for (int j = i; j < NN; j += stride) g_deg[j] = 0;
    if (i == 0) g_idx32 = 0;
}

// ---------------- K1: detect index dtype ----------------
__global__ void detect_kernel(const unsigned long long* __restrict__ s,
                              const unsigned long long* __restrict__ d,
                              int nwords) {
    int i = blockIdx.x * blockDim.x + threadIdx.x;
    int stride = gridDim.x * blockDim.x;
    int found = 0;
    for (int j = i; j < nwords; j += stride) {
        if ((s[j] >> 32) | (d[j] >> 32)) { found = 1; break; }
    }
    if (found) g_idx32 = 1;
}

// ---------------- K2: split-bf16 HMMA GEMM (+ fused el/er epilogue) -------
// C[128-tile,128] = feat[128,256] @ W^T using mma.sync m16n8k16 bf16.
// blockIdx.y == 0 -> ft (also computes el/er), == 1 -> res.
// CTA: 256 threads = 8 warps; warp grid 4(m) x 2(n); warp tile 32x64.
#define AST 40   // smem row stride in bf16 elements (80B, conflict-free ldmatrix)

__global__ __launch_bounds__(256, 1)
void gemm_mma_kernel(const float* __restrict__ feat,
                     const float* __restrict__ fc_w,
                     const float* __restrict__ res_w,
                     const float* __restrict__ attn_l,
                     const float* __restrict__ attn_r) {
    __shared__ __align__(16) __nv_bfloat16 sAh[128 * AST];
    __shared__ __align__(16) __nv_bfloat16 sAl[128 * AST];
    __shared__ __align__(16) __nv_bfloat16 sBh[128 * AST];
    __shared__ __align__(16) __nv_bfloat16 sBl[128 * AST];
    __shared__ float s_attn[2 * HD];

    const int tid = threadIdx.x;
    const int wid = tid >> 5;
    const int lane = tid & 31;
    const int wm = wid & 3;          // m-warp: rows wm*32..+31
    const int wn = wid >> 2;         // n-warp: cols wn*64..+63
    const int isft = (blockIdx.y == 0);
    const int block_m = blockIdx.x * 128;
    const float* __restrict__ W = isft ? fc_w : res_w;
    float* __restrict__ C = isft ? g_ft : g_res;

    if (isft && tid < 128) {
        s_attn[tid] = attn_l[tid];
        s_attn[HD + tid] = attn_r[tid];
    }

    // ---- load mapping: thread pair per row; 16 consecutive k-floats ----
    const int arow = tid >> 1;               // 0..127
    const int acol0 = (tid & 1) * 16;        // 0 or 16
    const int gm = block_m + arow;
    const bool a_ok = (gm < NN);
    const float* __restrict__ Abase = feat + (size_t)(a_ok ? gm : 0) * KIN + acol0;
    const float* __restrict__ Bbase = W + (size_t)arow * KIN + acol0;

    float4 pa[4], pb[4];
#pragma unroll
    for (int j = 0; j < 4; j++) {
        pa[j] = a_ok ? *reinterpret_cast<const float4*>(Abase + j * 4)
                     : make_float4(0.f, 0.f, 0.f, 0.f);
        pb[j] = *reinterpret_cast<const float4*>(Bbase + j * 4);
    }

    float acc[2][8][4];
#pragma unroll
    for (int mb = 0; mb < 2; mb++)
#pragma unroll
        for (int nb = 0; nb < 8; nb++)
#pragma unroll
            for (int c = 0; c < 4; c++) acc[mb][nb][c] = 0.f;

    const uint32_t sAh_b = smem_u32(sAh), sAl_b = smem_u32(sAl);
    const uint32_t sBh_b = smem_u32(sBh), sBl_b = smem_u32(sBl);
    // ldmatrix lane-address components
    const int a_row_l = (lane & 15);
    const int a_chunk = (lane >> 4);               // 0/1 -> k-halves
    const int b_kchunk = (lane >> 3) & 1;
    const int b_nhalf = (lane >> 4) & 1;           // which n8 of the pair
    const int b_row_l = (lane & 7);

#pragma unroll 1
    for (int kk = 0; kk < KIN; kk += 32) {
        // ---- convert prefetched regs -> smem (hi/lo split) ----
        {
            uint32_t h[8], l[8];
            split_pack(pa[0].x, pa[0].y, h[0], l[0]);
            split_pack(pa[0].z, pa[0].w, h[1], l[1]);
            split_pack(pa[1].x, pa[1].y, h[2], l[2]);
            split_pack(pa[1].z, pa[1].w, h[3], l[3]);
            split_pack(pa[2].x, pa[2].y, h[4], l[4]);
            split_pack(pa[2].z, pa[2].w, h[5], l[5]);
            split_pack(pa[3].x, pa[3].y, h[6], l[6]);
            split_pack(pa[3].z, pa[3].w, h[7], l[7]);
            uint4* ph = reinterpret_cast<uint4*>(&sAh[arow * AST + acol0]);
            uint4* pl = reinterpret_cast<uint4*>(&sAl[arow * AST + acol0]);
            ph[0] = make_uint4(h[0], h[1], h[2], h[3]);
            ph[1] = make_uint4(h[4], h[5], h[6], h[7]);
            pl[0] = make_uint4(l[0], l[1], l[2], l[3]);
            pl[1] = make_uint4(l[4], l[5], l[6], l[7]);

            split_pack(pb[0].x, pb[0].y, h[0], l[0]);
            split_pack(pb[0].z, pb[0].w, h[1], l[1]);
            split_pack(pb[1].x, pb[1].y, h[2], l[2]);
            split_pack(pb[1].z, pb[1].w, h[3], l[3]);
            split_pack(pb[2].x, pb[2].y, h[4], l[4]);
            split_pack(pb[2].z, pb[2].w, h[5], l[5]);
            split_pack(pb[3].x, pb[3].y, h[6], l[6]);
            split_pack(pb[3].z, pb[3].w, h[7], l[7]);
            uint4* qh = reinterpret_cast<uint4*>(&sBh[arow * AST + acol0]);
            uint4* ql = reinterpret_cast<uint4*>(&sBl[arow * AST + acol0]);
            qh[0] = make_uint4(h[0], h[1], h[2], h[3]);
            qh[1] = make_uint4(h[4], h[5], h[6], h[7]);
            ql[0] = make_uint4(l[0], l[1], l[2], l[3]);
            ql[1] = make_uint4(l[4], l[5], l[6], l[7]);
        }
        __syncthreads();

        // ---- prefetch next chunk (overlaps with MMA below) ----
        if (kk + 32 < KIN) {
#pragma unroll
            for (int j = 0; j < 4; j++) {
                pa[j] = a_ok ? *reinterpret_cast<const float4*>(Abase + kk + 32 + j * 4)
                             : make_float4(0.f, 0.f, 0.f, 0.f);
                pb[j] = *reinterpret_cast<const float4*>(Bbase + kk + 32 + j * 4);
            }
        }

        // ---- MMA over the two k16 steps of this chunk ----
#pragma unroll
        for (int k16 = 0; k16 < 32; k16 += 16) {
            uint32_t ah[2][4], al[2][4], bh[8][2], bl[8][2];
#pragma unroll
            for (int mb = 0; mb < 2; mb++) {
                uint32_t off = (uint32_t)(((wm * 32 + mb * 16 + a_row_l) * AST +
                                           k16 + a_chunk * 8) * 2);
                ldsm_x4(ah[mb], sAh_b + off);
                ldsm_x4(al[mb], sAl_b + off);
            }
#pragma unroll
            for (int j = 0; j < 4; j++) {
                int nrow = wn * 64 + (2 * j + b_nhalf) * 8 + b_row_l;
                uint32_t off = (uint32_t)((nrow * AST + k16 + b_kchunk * 8) * 2);
                uint32_t t[4];
                ldsm_x4(t, sBh_b + off);
                bh[2 * j][0] = t[0]; bh[2 * j][1] = t[1];
                bh[2 * j + 1][0] = t[2]; bh[2 * j + 1][1] = t[3];
                ldsm_x4(t, sBl_b + off);
                bl[2 * j][0] = t[0]; bl[2 * j][1] = t[1];
                bl[2 * j + 1][0] = t[2]; bl[2 * j + 1][1] = t[3];
            }
#pragma unroll
            for (int mb = 0; mb < 2; mb++)
#pragma unroll
                for (int nb = 0; nb < 8; nb++) {
                    mma_bf16(acc[mb][nb], ah[mb], bh[nb]);
                    mma_bf16(acc[mb][nb], al[mb], bh[nb]);
                    mma_bf16(acc[mb][nb], ah[mb], bl[nb]);
                }
        }
        __syncthreads();
    }

    // ---- epilogue: store C + fused el/er (quad-shuffle reduction) ----
    const int qrow = lane >> 2;      // 0..7
    const int qcol = lane & 3;       // 0..3
#pragma unroll
    for (int mb = 0; mb < 2; mb++) {
        int r0 = block_m + wm * 32 + mb * 16 + qrow;
#pragma unroll
        for (int nb = 0; nb < 8; nb++) {
            int col = wn * 64 + nb * 8 + qcol * 2;
            if (r0 < NN)
                *reinterpret_cast<float2*>(C + (size_t)r0 * HD + col) =
                    make_float2(acc[mb][nb][0], acc[mb][nb][1]);
            if (r0 + 8 < NN)
                *reinterpret_cast<float2*>(C + (size_t)(r0 + 8) * HD + col) =
                    make_float2(acc[mb][nb][2], acc[mb][nb][3]);
        }
        if (isft) {
#pragma unroll
            for (int rr = 0; rr < 2; rr++) {
                int row = r0 + rr * 8;
#pragma unroll
                for (int hh = 0; hh < 2; hh++) {
                    float el = 0.f, er = 0.f;
#pragma unroll
                    for (int nb4 = 0; nb4 < 4; nb4++) {
                        int nb = hh * 4 + nb4;
                        int col = wn * 64 + nb * 8 + qcol * 2;
                        float v0 = acc[mb][nb][rr * 2];
                        float v1 = acc[mb][nb][rr * 2 + 1];
                        el = fmaf(v0, s_attn[col], el);
                        el = fmaf(v1, s_attn[col + 1], el);
                        er = fmaf(v0, s_attn[HD + col], er);
                        er = fmaf(v1, s_attn[HD + col + 1], er);
                    }
                    el += __shfl_xor_sync(0xffffffffu, el, 1);
                    el += __shfl_xor_sync(0xffffffffu, el, 2);
                    er += __shfl_xor_sync(0xffffffffu, er, 1);
                    er += __shfl_xor_sync(0xffffffffu, er, 2);
                    if (qcol == 0 && row < NN) {
                        int head = wn * 2 + hh;
                        g_el[row * NHEAD + head] = el;
                        g_er[row * NHEAD + head] = er;
                    }
                }
            }
        }
    }
}

// ---------------- K4: degree histogram ----------------
__global__ void hist_kernel(const void* __restrict__ dst) {
    int is32 = g_idx32;
    int i = blockIdx.x * blockDim.x + threadIdx.x;
    int stride = gridDim.x * blockDim.x;
    for (int e = i; e < EE; e += stride) {
        int d = load_idx(dst, e, is32);
        atomicAdd(&g_deg[d], 1);
    }
}

// ---------------- K5a: per-block sums for scan ----------------
__global__ void block_sums_kernel() {
    __shared__ int sh[32];
    int i = blockIdx.x * 1024 + threadIdx.x;
    int v = (i < NN) ? g_deg[i] : 0;
#pragma unroll
    for (int o = 16; o > 0; o >>= 1) v += __shfl_down_sync(0xffffffffu, v, o);
    if ((threadIdx.x & 31) == 0) sh[threadIdx.x >> 5] = v;
    __syncthreads();
    if (threadIdx.x < 32) {
        int w = sh[threadIdx.x];
#pragma unroll
        for (int o = 16; o > 0; o >>= 1) w += __shfl_down_sync(0xffffffffu, w, o);
        if (threadIdx.x == 0) g_bsum[blockIdx.x] = w;
    }
}

// ---------------- K5b: exclusive scan of block sums (tiny) ----------------
__global__ void scan_sums_kernel() {
    if (threadIdx.x == 0 && blockIdx.x == 0) {
        int running = 0;
        for (int b = 0; b < NB_SCAN; b++) {
            int t = g_bsum[b];
            g_bsum[b] = running;
            running += t;
        }
    }
}

// ---------------- K5c: per-block exclusive scan + offset ----------------
__global__ void scan_final_kernel() {
    __shared__ int sh[1024];
    int i = blockIdx.x * 1024 + threadIdx.x;
    int tid = threadIdx.x;
    int v = (i < NN) ? g_deg[i] : 0;
    int x = v;
    sh[tid] = x;
    __syncthreads();
#pragma unroll
    for (int off = 1; off < 1024; off <<= 1) {
        int y = (tid >= off) ? sh[tid - off] : 0;
        __syncthreads();
        x += y;
        sh[tid] = x;
        __syncthreads();
    }
    if (i < NN) {
        int excl = x - v + g_bsum[blockIdx.x];
        g_rowptr[i] = excl;
        g_fill[i] = excl;
    }
}

// ---------------- K6: scatter edges into CSR (by dst) ----------------
__global__ void scatter_kernel(const void* __restrict__ src,
                               const void* __restrict__ dst) {
    int is32 = g_idx32;
    int i = blockIdx.x * blockDim.x + threadIdx.x;
    int stride = gridDim.x * blockDim.x;
    for (int e = i; e < EE; e += stride) {
        int d = load_idx(dst, e, is32);
        int s = load_idx(src, e, is32);
        int pos = atomicAdd(&g_fill[d], 1);
        g_esrc[pos] = s;
    }
}

// ---------------- K7: fused edge-softmax + aggregation + residual ----------
__global__ __launch_bounds__(256)
void agg_kernel(float* __restrict__ out, int out_size) {
    int gwarp = (blockIdx.x * blockDim.x + threadIdx.x) >> 5;
    int lane = threadIdx.x & 31;
    if (gwarp >= NN * NHEAD) return;
    int n = gwarp >> 2;
    int h = gwarp & 3;

    int start = g_rowptr[n];
    int len = g_deg[n];
    float ernh = g_er[n * NHEAD + h];

    const float* __restrict__ ftp = g_ft + (size_t)h * DDIM + lane;
    float acc = 0.f, sume = 0.f;
    int s_next = (len > 0) ? g_esrc[start] : 0;
    for (int i = 0; i < len; i++) {
        int s = s_next;
        if (i + 1 < len) s_next = g_esrc[start + i + 1];
        float e = g_el[s * NHEAD + h] + ernh;
        e = (e > 0.f) ? e : NEG_SLOPE * e;
        float ex = expf(e);
        sume += ex;
        acc = fmaf(ex, ftp[(size_t)s * HD], acc);
    }
    float a = (len > 0) ? (acc / sume) : 0.f;

    size_t o = (size_t)n * HD + h * DDIM + lane;
    float r = g_res[o];
    out[o] = a + r;                                   // rst
    if (out_size >= 2 * NN * HD)
        out[(size_t)NN * HD + o] = a;                 // agg (dglrst)
}

// ---------------- launch ----------------
extern "C" void kernel_launch(void* const* d_in, const int* in_sizes, int n_in,
                              void* d_out, int out_size) {
    const float* feat   = (const float*)d_in[0];
    const void*  src    = d_in[1];
    const void*  dst    = d_in[2];
    const float* fc_w   = (const float*)d_in[3];
    const float* attn_l = (const float*)d_in[4];
    const float* attn_r = (const float*)d_in[5];
    const float* res_w  = (const float*)d_in[6];
    float* out = (float*)d_out;

    zero_kernel<<<256, 256>>>();
    detect_kernel<<<256, 256>>>((const unsigned long long*)src,
                                (const unsigned long long*)dst, EE / 2);

    dim3 ggrid((NN + 127) / 128, 2);
    gemm_mma_kernel<<<ggrid, 256>>>(feat, fc_w, res_w, attn_l, attn_r);

    hist_kernel<<<512, 256>>>(dst);
    block_sums_kernel<<<NB_SCAN, 1024>>>();
    scan_sums_kernel<<<1, 32>>>();
    scan_final_kernel<<<NB_SCAN, 1024>>>();
    scatter_kernel<<<512, 256>>>(src, dst);

    int total_warps = NN * NHEAD;                      // 400000
    int blocks = (total_warps * 32 + 255) / 256;       // 50000
    agg_kernel<<<blocks, 256>>>(out, out_size);
}

// round 16
// speedup vs baseline: 1.8444x; 1.3519x over previous
#include <cuda_runtime.h>
#include <cuda_bf16.h>
#include <stdint.h>
#include <math.h>

// Problem constants (fixed by the dataset)
#define NN 100000           // nodes
#define EE 1600000          // edges
#define KIN 256             // in_feats
#define HD  128             // H*D
#define NHEAD 4
#define DDIM 32
#define NEG_SLOPE 0.2f

#define NB_SCAN 98          // ceil(NN/1024)

// ---------------- device scratch (static, no allocations) ----------------
__device__ float g_ft[(size_t)NN * HD];    // projected features [N,128]
__device__ float g_res[(size_t)NN * HD];   // residual projection [N,128]
__device__ float g_el[NN * NHEAD];
__device__ float g_er[NN * NHEAD];
__device__ int   g_deg[NN];
__device__ int   g_rowptr[NN];
__device__ int   g_fill[NN];
__device__ int   g_esrc[EE];
__device__ int   g_bsum[NB_SCAN + 1];
__device__ int   g_idx32 = 0;              // sticky: set to 1 iff indices are int32
// pre-split weights: [0..32767] = fc_w, [32768..] = res_w (row-major [128,256])
__device__ __align__(16) __nv_bfloat16 g_wh[2 * 32768];
__device__ __align__(16) __nv_bfloat16 g_wl[2 * 32768];

// ---------------- helpers ----------------
__device__ __forceinline__ int load_idx(const void* p, int i, int is32) {
    if (is32) return ((const int*)p)[i];
    return (int)(((const long long*)p)[i]);
}

__device__ __forceinline__ uint32_t smem_u32(const void* p) {
    uint32_t a;
    asm("{ .reg .u64 t; cvta.to.shared.u64 t, %1; cvt.u32.u64 %0, t; }"
        : "=r"(a) : "l"(p));
    return a;
}

__device__ __forceinline__ void ldsm_x4(uint32_t* r, uint32_t addr) {
    asm volatile("ldmatrix.sync.aligned.m8n8.x4.shared.b16 {%0,%1,%2,%3}, [%4];"
                 : "=r"(r[0]), "=r"(r[1]), "=r"(r[2]), "=r"(r[3]) : "r"(addr));
}

__device__ __forceinline__ void mma_bf16(float* d, const uint32_t* a,
                                         const uint32_t* b) {
    asm volatile(
        "mma.sync.aligned.m16n8k16.row.col.f32.bf16.bf16.f32 "
        "{%0,%1,%2,%3}, {%4,%5,%6,%7}, {%8,%9}, {%0,%1,%2,%3};\n"
        : "+f"(d[0]), "+f"(d[1]), "+f"(d[2]), "+f"(d[3])
        : "r"(a[0]), "r"(a[1]), "r"(a[2]), "r"(a[3]), "r"(b[0]), "r"(b[1]));
}

// split fp32 pair -> packed bf16x2 hi / lo
__device__ __forceinline__ void split_pack(float v0, float v1,
                                           uint32_t& hi, uint32_t& lo) {
    __nv_bfloat16 h0 = __float2bfloat16_rn(v0);
    __nv_bfloat16 h1 = __float2bfloat16_rn(v1);
    __nv_bfloat16 l0 = __float2bfloat16_rn(v0 - __bfloat162float(h0));
    __nv_bfloat16 l1 = __float2bfloat16_rn(v1 - __bfloat162float(h1));
    hi = ((uint32_t)__bfloat16_as_ushort(h1) << 16) | __bfloat16_as_ushort(h0);
    lo = ((uint32_t)__bfloat16_as_ushort(l1) << 16) | __bfloat16_as_ushort(l0);
}

// ---------------- K0: zero deg + sticky index-dtype detection --------------
__global__ void init_kernel(const unsigned long long* __restrict__ s,
                            const unsigned long long* __restrict__ d,
                            int nwords) {
    int i = blockIdx.x * blockDim.x + threadIdx.x;
    int stride = gridDim.x * blockDim.x;
    for (int j = i; j < NN; j += stride) g_deg[j] = 0;
    int found = 0;
    for (int j = i; j < nwords; j += stride) {
        if ((s[j] >> 32) | (d[j] >> 32)) { found = 1; break; }
    }
    if (found) g_idx32 = 1;   // idempotent across graph replays
}

// ---------------- K1: pre-split weights into bf16 hi/lo --------------------
__global__ void presplit_kernel(const float* __restrict__ fc_w,
                                const float* __restrict__ res_w) {
    int i = blockIdx.x * blockDim.x + threadIdx.x;
    if (i >= 32768) return;
    float v = fc_w[i];
    __nv_bfloat16 h = __float2bfloat16_rn(v);
    g_wh[i] = h;
    g_wl[i] = __float2bfloat16_rn(v - __bfloat162float(h));
    v = res_w[i];
    h = __float2bfloat16_rn(v);
    g_wh[32768 + i] = h;
    g_wl[32768 + i] = __float2bfloat16_rn(v - __bfloat162float(h));
}

// ---------------- K2: split-bf16 HMMA GEMM (+ fused el/er epilogue) -------
// C[128-tile,128] = feat[128,256] @ W^T using mma.sync m16n8k16 bf16.
// blockIdx.y == 0 -> ft (also computes el/er), == 1 -> res.
// CTA: 256 threads = 8 warps; warp grid 4(m) x 2(n); warp tile 32x64.
#define AST 40   // smem row stride in bf16 elements (80B, conflict-free ldmatrix)

__global__ __launch_bounds__(256, 1)
void gemm_mma_kernel(const float* __restrict__ feat,
                     const float* __restrict__ attn_l,
                     const float* __restrict__ attn_r) {
    __shared__ __align__(16) __nv_bfloat16 sAh[128 * AST];
    __shared__ __align__(16) __nv_bfloat16 sAl[128 * AST];
    __shared__ __align__(16) __nv_bfloat16 sBh[128 * AST];
    __shared__ __align__(16) __nv_bfloat16 sBl[128 * AST];
    __shared__ float s_attn[2 * HD];

    const int tid = threadIdx.x;
    const int wid = tid >> 5;
    const int lane = tid & 31;
    const int wm = wid & 3;          // m-warp: rows wm*32..+31
    const int wn = wid >> 2;         // n-warp: cols wn*64..+63
    const int isft = (blockIdx.y == 0);
    const int block_m = blockIdx.x * 128;
    float* __restrict__ C = isft ? g_ft : g_res;

    if (isft && tid < 128) {
        s_attn[tid] = attn_l[tid];
        s_attn[HD + tid] = attn_r[tid];
    }

    // ---- load mapping: thread pair per row; 16 consecutive k-elements ----
    const int arow = tid >> 1;               // 0..127
    const int acol0 = (tid & 1) * 16;        // 0 or 16
    const int gm = block_m + arow;
    const bool a_ok = (gm < NN);
    const float* __restrict__ Abase = feat + (size_t)(a_ok ? gm : 0) * KIN + acol0;
    const __nv_bfloat16* __restrict__ Bh_base =
        g_wh + (isft ? 0 : 32768) + arow * KIN + acol0;
    const __nv_bfloat16* __restrict__ Bl_base =
        g_wl + (isft ? 0 : 32768) + arow * KIN + acol0;

    float4 pa[4];
    uint4 pbh[2], pbl[2];
#pragma unroll
    for (int j = 0; j < 4; j++)
        pa[j] = a_ok ? *reinterpret_cast<const float4*>(Abase + j * 4)
                     : make_float4(0.f, 0.f, 0.f, 0.f);
    pbh[0] = *reinterpret_cast<const uint4*>(Bh_base);
    pbh[1] = *reinterpret_cast<const uint4*>(Bh_base + 8);
    pbl[0] = *reinterpret_cast<const uint4*>(Bl_base);
    pbl[1] = *reinterpret_cast<const uint4*>(Bl_base + 8);

    float acc[2][8][4];
#pragma unroll
    for (int mb = 0; mb < 2; mb++)
#pragma unroll
        for (int nb = 0; nb < 8; nb++)
#pragma unroll
            for (int c = 0; c < 4; c++) acc[mb][nb][c] = 0.f;

    const uint32_t sAh_b = smem_u32(sAh), sAl_b = smem_u32(sAl);
    const uint32_t sBh_b = smem_u32(sBh), sBl_b = smem_u32(sBl);
    // ldmatrix lane-address components
    const int a_row_l = (lane & 15);
    const int a_chunk = (lane >> 4);               // 0/1 -> k-halves
    const int b_kchunk = (lane >> 3) & 1;
    const int b_nhalf = (lane >> 4) & 1;           // which n8 of the pair
    const int b_row_l = (lane & 7);

#pragma unroll 1
    for (int kk = 0; kk < KIN; kk += 32) {
        // ---- write prefetched data to smem (A: hi/lo split; B: direct) ----
        {
            uint32_t h[8], l[8];
            split_pack(pa[0].x, pa[0].y, h[0], l[0]);
            split_pack(pa[0].z, pa[0].w, h[1], l[1]);
            split_pack(pa[1].x, pa[1].y, h[2], l[2]);
            split_pack(pa[1].z, pa[1].w, h[3], l[3]);
            split_pack(pa[2].x, pa[2].y, h[4], l[4]);
            split_pack(pa[2].z, pa[2].w, h[5], l[5]);
            split_pack(pa[3].x, pa[3].y, h[6], l[6]);
            split_pack(pa[3].z, pa[3].w, h[7], l[7]);
            uint4* ph = reinterpret_cast<uint4*>(&sAh[arow * AST + acol0]);
            uint4* pl = reinterpret_cast<uint4*>(&sAl[arow * AST + acol0]);
            ph[0] = make_uint4(h[0], h[1], h[2], h[3]);
            ph[1] = make_uint4(h[4], h[5], h[6], h[7]);
            pl[0] = make_uint4(l[0], l[1], l[2], l[3]);
            pl[1] = make_uint4(l[4], l[5], l[6], l[7]);

            uint4* qh = reinterpret_cast<uint4*>(&sBh[arow * AST + acol0]);
            uint4* ql = reinterpret_cast<uint4*>(&sBl[arow * AST + acol0]);
            qh[0] = pbh[0]; qh[1] = pbh[1];
            ql[0] = pbl[0]; ql[1] = pbl[1];
        }
        __syncthreads();

        // ---- prefetch next chunk (overlaps with MMA below) ----
        if (kk + 32 < KIN) {
#pragma unroll
            for (int j = 0; j < 4; j++)
                pa[j] = a_ok ? *reinterpret_cast<const float4*>(Abase + kk + 32 + j * 4)
                             : make_float4(0.f, 0.f, 0.f, 0.f);
            pbh[0] = *reinterpret_cast<const uint4*>(Bh_base + kk + 32);
            pbh[1] = *reinterpret_cast<const uint4*>(Bh_base + kk + 40);
            pbl[0] = *reinterpret_cast<const uint4*>(Bl_base + kk + 32);
            pbl[1] = *reinterpret_cast<const uint4*>(Bl_base + kk + 40);
        }

        // ---- MMA over the two k16 steps of this chunk ----
#pragma unroll
        for (int k16 = 0; k16 < 32; k16 += 16) {
            uint32_t ah[2][4], al[2][4], bh[8][2], bl[8][2];
#pragma unroll
            for (int mb = 0; mb < 2; mb++) {
                uint32_t off = (uint32_t)(((wm * 32 + mb * 16 + a_row_l) * AST +
                                           k16 + a_chunk * 8) * 2);
                ldsm_x4(ah[mb], sAh_b + off);
                ldsm_x4(al[mb], sAl_b + off);
            }
#pragma unroll
            for (int j = 0; j < 4; j++) {
                int nrow = wn * 64 + (2 * j + b_nhalf) * 8 + b_row_l;
                uint32_t off = (uint32_t)((nrow * AST + k16 + b_kchunk * 8) * 2);
                uint32_t t[4];
                ldsm_x4(t, sBh_b + off);
                bh[2 * j][0] = t[0]; bh[2 * j][1] = t[1];
                bh[2 * j + 1][0] = t[2]; bh[2 * j + 1][1] = t[3];
                ldsm_x4(t, sBl_b + off);
                bl[2 * j][0] = t[0]; bl[2 * j][1] = t[1];
                bl[2 * j + 1][0] = t[2]; bl[2 * j + 1][1] = t[3];
            }
#pragma unroll
            for (int mb = 0; mb < 2; mb++)
#pragma unroll
                for (int nb = 0; nb < 8; nb++) {
                    mma_bf16(acc[mb][nb], ah[mb], bh[nb]);
                    mma_bf16(acc[mb][nb], al[mb], bh[nb]);
                    mma_bf16(acc[mb][nb], ah[mb], bl[nb]);
                }
        }
        __syncthreads();
    }

    // ---- epilogue: store C + fused el/er (quad-shuffle reduction) ----
    const int qrow = lane >> 2;      // 0..7
    const int qcol = lane & 3;       // 0..3
#pragma unroll
    for (int mb = 0; mb < 2; mb++) {
        int r0 = block_m + wm * 32 + mb * 16 + qrow;
#pragma unroll
        for (int nb = 0; nb < 8; nb++) {
            int col = wn * 64 + nb * 8 + qcol * 2;
            if (r0 < NN)
                *reinterpret_cast<float2*>(C + (size_t)r0 * HD + col) =
                    make_float2(acc[mb][nb][0], acc[mb][nb][1]);
            if (r0 + 8 < NN)
                *reinterpret_cast<float2*>(C + (size_t)(r0 + 8) * HD + col) =
                    make_float2(acc[mb][nb][2], acc[mb][nb][3]);
        }
        if (isft) {
#pragma unroll
            for (int rr = 0; rr < 2; rr++) {
                int row = r0 + rr * 8;
#pragma unroll
                for (int hh = 0; hh < 2; hh++) {
                    float el = 0.f, er = 0.f;
#pragma unroll
                    for (int nb4 = 0; nb4 < 4; nb4++) {
                        int nb = hh * 4 + nb4;
                        int col = wn * 64 + nb * 8 + qcol * 2;
                        float v0 = acc[mb][nb][rr * 2];
                        float v1 = acc[mb][nb][rr * 2 + 1];
                        el = fmaf(v0, s_attn[col], el);
                        el = fmaf(v1, s_attn[col + 1], el);
                        er = fmaf(v0, s_attn[HD + col], er);
                        er = fmaf(v1, s_attn[HD + col + 1], er);
                    }
                    el += __shfl_xor_sync(0xffffffffu, el, 1);
                    el += __shfl_xor_sync(0xffffffffu, el, 2);
                    er += __shfl_xor_sync(0xffffffffu, er, 1);
                    er += __shfl_xor_sync(0xffffffffu, er, 2);
                    if (qcol == 0 && row < NN) {
                        int head = wn * 2 + hh;
                        g_el[row * NHEAD + head] = el;
                        g_er[row * NHEAD + head] = er;
                    }
                }
            }
        }
    }
}

// ---------------- K4: degree histogram ----------------
__global__ void hist_kernel(const void* __restrict__ dst) {
    int is32 = g_idx32;
    int i = blockIdx.x * blockDim.x + threadIdx.x;
    int stride = gridDim.x * blockDim.x;
    for (int e = i; e < EE; e += stride) {
        int d = load_idx(dst, e, is32);
        atomicAdd(&g_deg[d], 1);
    }
}

// ---------------- K5a: per-block sums for scan ----------------
__global__ void block_sums_kernel() {
    __shared__ int sh[32];
    int i = blockIdx.x * 1024 + threadIdx.x;
    int v = (i < NN) ? g_deg[i] : 0;
#pragma unroll
    for (int o = 16; o > 0; o >>= 1) v += __shfl_down_sync(0xffffffffu, v, o);
    if ((threadIdx.x & 31) == 0) sh[threadIdx.x >> 5] = v;
    __syncthreads();
    if (threadIdx.x < 32) {
        int w = sh[threadIdx.x];
#pragma unroll
        for (int o = 16; o > 0; o >>= 1) w += __shfl_down_sync(0xffffffffu, w, o);
        if (threadIdx.x == 0) g_bsum[blockIdx.x] = w;
    }
}

// ---------------- K5b: exclusive scan of block sums (tiny) ----------------
__global__ void scan_sums_kernel() {
    if (threadIdx.x == 0 && blockIdx.x == 0) {
        int running = 0;
        for (int b = 0; b < NB_SCAN; b++) {
            int t = g_bsum[b];
            g_bsum[b] = running;
            running += t;
        }
    }
}

// ---------------- K5c: per-block exclusive scan + offset ----------------
__global__ void scan_final_kernel() {
    __shared__ int sh[1024];
    int i = blockIdx.x * 1024 + threadIdx.x;
    int tid = threadIdx.x;
    int v = (i < NN) ? g_deg[i] : 0;
    int x = v;
    sh[tid] = x;
    __syncthreads();
#pragma unroll
    for (int off = 1; off < 1024; off <<= 1) {
        int y = (tid >= off) ? sh[tid - off] : 0;
        __syncthreads();
        x += y;
        sh[tid] = x;
        __syncthreads();
    }
    if (i < NN) {
        int excl = x - v + g_bsum[blockIdx.x];
        g_rowptr[i] = excl;
        g_fill[i] = excl;
    }
}

// ---------------- K6: scatter edges into CSR (by dst) ----------------
__global__ void scatter_kernel(const void* __restrict__ src,
                               const void* __restrict__ dst) {
    int is32 = g_idx32;
    int i = blockIdx.x * blockDim.x + threadIdx.x;
    int stride = gridDim.x * blockDim.x;
    for (int e = i; e < EE; e += stride) {
        int d = load_idx(dst, e, is32);
        int s = load_idx(src, e, is32);
        int pos = atomicAdd(&g_fill[d], 1);
        g_esrc[pos] = s;
    }
}

// ---------------- K7: fused edge-softmax + aggregation + residual ----------
// One warp per node, all 4 heads at once (lane = d). Per edge: 1 index load,
// 1 float4 el broadcast, 4 independent 128B ft gathers -> 4x the MLP of the
// old warp-per-(node,head) layout, and 4x less esrc/el traffic.
__global__ __launch_bounds__(256)
void agg_kernel(float* __restrict__ out, int out_size) {
    int n = (blockIdx.x * blockDim.x + threadIdx.x) >> 5;
    int lane = threadIdx.x & 31;
    if (n >= NN) return;

    int start = g_rowptr[n];
    int len = g_deg[n];
    const float4 ern = *reinterpret_cast<const float4*>(&g_er[n * NHEAD]);
    const float4* __restrict__ el4 = reinterpret_cast<const float4*>(g_el);

    float a0 = 0.f, a1 = 0.f, a2 = 0.f, a3 = 0.f;
    float s0 = 0.f, s1 = 0.f, s2 = 0.f, s3 = 0.f;

    int sA = (len > 0) ? g_esrc[start] : 0;
    float4 eA = el4[sA];
    for (int i = 0; i < len; i++) {
        int s = sA;
        float4 ev = eA;
        if (i + 1 < len) {
            sA = g_esrc[start + i + 1];
            eA = el4[sA];
        }
        const float* __restrict__ fr = g_ft + (size_t)s * HD + lane;
        float f0 = fr[0];
        float f1 = fr[32];
        float f2 = fr[64];
        float f3 = fr[96];
        float e0 = ev.x + ern.x; e0 = (e0 > 0.f) ? e0 : NEG_SLOPE * e0;
        float e1 = ev.y + ern.y; e1 = (e1 > 0.f) ? e1 : NEG_SLOPE * e1;
        float e2 = ev.z + ern.z; e2 = (e2 > 0.f) ? e2 : NEG_SLOPE * e2;
        float e3 = ev.w + ern.w; e3 = (e3 > 0.f) ? e3 : NEG_SLOPE * e3;
        float x0 = __expf(e0), x1 = __expf(e1), x2 = __expf(e2), x3 = __expf(e3);
        s0 += x0; s1 += x1; s2 += x2; s3 += x3;
        a0 = fmaf(x0, f0, a0);
        a1 = fmaf(x1, f1, a1);
        a2 = fmaf(x2, f2, a2);
        a3 = fmaf(x3, f3, a3);
    }
    float r0 = len ? a0 / s0 : 0.f;
    float r1 = len ? a1 / s1 : 0.f;
    float r2 = len ? a2 / s2 : 0.f;
    float r3 = len ? a3 / s3 : 0.f;

    size_t o = (size_t)n * HD + lane;
    out[o]      = r0 + g_res[o];
    out[o + 32] = r1 + g_res[o + 32];
    out[o + 64] = r2 + g_res[o + 64];
    out[o + 96] = r3 + g_res[o + 96];
    if (out_size >= 2 * NN * HD) {
        size_t o2 = (size_t)NN * HD + o;
        out[o2]      = r0;
        out[o2 + 32] = r1;
        out[o2 + 64] = r2;
        out[o2 + 96] = r3;
    }
}

// ---------------- launch ----------------
extern "C" void kernel_launch(void* const* d_in, const int* in_sizes, int n_in,
                              void* d_out, int out_size) {
    const float* feat   = (const float*)d_in[0];
    const void*  src    = d_in[1];
    const void*  dst    = d_in[2];
    const float* fc_w   = (const float*)d_in[3];
    const float* attn_l = (const float*)d_in[4];
    const float* attn_r = (const float*)d_in[5];
    const float* res_w  = (const float*)d_in[6];
    float* out = (float*)d_out;

    init_kernel<<<512, 256>>>((const unsigned long long*)src,
                              (const unsigned long long*)dst, EE / 2);
    presplit_kernel<<<128, 256>>>(fc_w, res_w);

    dim3 ggrid((NN + 127) / 128, 2);
    gemm_mma_kernel<<<ggrid, 256>>>(feat, attn_l, attn_r);

    hist_kernel<<<2048, 256>>>(dst);
    block_sums_kernel<<<NB_SCAN, 1024>>>();
    scan_sums_kernel<<<1, 32>>>();
    scan_final_kernel<<<NB_SCAN, 1024>>>();
    scatter_kernel<<<2048, 256>>>(src, dst);

    int blocks = (NN * 32 + 255) / 256;   // one warp per node
    agg_kernel<<<blocks, 256>>>(out, out_size);
}

// round 17
// speedup vs baseline: 1.9186x; 1.0403x over previous
#include <cuda_runtime.h>
#include <cuda_bf16.h>
#include <stdint.h>
#include <math.h>

// Problem constants (fixed by the dataset)
#define NN 100000           // nodes
#define EE 1600000          // edges
#define KIN 256             // in_feats
#define HD  128             // H*D
#define NHEAD 4
#define DDIM 32
#define NEG_SLOPE 0.2f

#define NB_SCAN 98          // ceil(NN/1024)

// ---------------- device scratch (static, no allocations) ----------------
__device__ float g_ft[(size_t)NN * HD];    // projected features [N,128]
__device__ float g_res[(size_t)NN * HD];   // residual projection [N,128]
__device__ float g_el[NN * NHEAD];
__device__ float g_er[NN * NHEAD];
__device__ int   g_deg[NN];
__device__ int   g_rowptr[NN];
__device__ int   g_fill[NN];
__device__ int   g_esrc[EE];
__device__ int   g_bsum[NB_SCAN + 1];
__device__ int   g_idx32;                  // 1 iff indices are int32
// pre-split weights: [0..32767] = fc_w, [32768..] = res_w (row-major [128,256])
__device__ __align__(16) __nv_bfloat16 g_wh[2 * 32768];
__device__ __align__(16) __nv_bfloat16 g_wl[2 * 32768];

// ---------------- helpers ----------------
__device__ __forceinline__ int load_idx(const void* p, int i, int is32) {
    if (is32) return ((const int*)p)[i];
    return (int)(((const long long*)p)[i]);
}

__device__ __forceinline__ uint32_t smem_u32(const void* p) {
    uint32_t a;
    asm("{ .reg .u64 t; cvta.to.shared.u64 t, %1; cvt.u32.u64 %0, t; }"
        : "=r"(a) : "l"(p));
    return a;
}

__device__ __forceinline__ void ldsm_x4(uint32_t* r, uint32_t addr) {
    asm volatile("ldmatrix.sync.aligned.m8n8.x4.shared.b16 {%0,%1,%2,%3}, [%4];"
                 : "=r"(r[0]), "=r"(r[1]), "=r"(r[2]), "=r"(r[3]) : "r"(addr));
}

__device__ __forceinline__ void mma_bf16(float* d, const uint32_t* a,
                                         const uint32_t* b) {
    asm volatile(
        "mma.sync.aligned.m16n8k16.row.col.f32.bf16.bf16.f32 "
        "{%0,%1,%2,%3}, {%4,%5,%6,%7}, {%8,%9}, {%0,%1,%2,%3};\n"
        : "+f"(d[0]), "+f"(d[1]), "+f"(d[2]), "+f"(d[3])
        : "r"(a[0]), "r"(a[1]), "r"(a[2]), "r"(a[3]), "r"(b[0]), "r"(b[1]));
}

// split fp32 pair -> packed bf16x2 hi / lo
__device__ __forceinline__ void split_pack(float v0, float v1,
                                           uint32_t& hi, uint32_t& lo) {
    __nv_bfloat16 h0 = __float2bfloat16_rn(v0);
    __nv_bfloat16 h1 = __float2bfloat16_rn(v1);
    __nv_bfloat16 l0 = __float2bfloat16_rn(v0 - __bfloat162float(h0));
    __nv_bfloat16 l1 = __float2bfloat16_rn(v1 - __bfloat162float(h1));
    hi = ((uint32_t)__bfloat16_as_ushort(h1) << 16) | __bfloat16_as_ushort(h0);
    lo = ((uint32_t)__bfloat16_as_ushort(l1) << 16) | __bfloat16_as_ushort(l0);
}

// ---------------- K0: zero degree array ------------------------------------
__global__ void zero_kernel() {
    int i = blockIdx.x * blockDim.x + threadIdx.x;
    if (i < NN) g_deg[i] = 0;
}

// ---------------- K1: sampled index-dtype detection -------------------------
// 2048 u64 words sampled from each buffer. If data is int32, a sampled high
// half is a uniform node id (zero w.p. 1e-5) -> P(all zero) ~ 0. Deterministic.
__global__ void detect_kernel(const unsigned long long* __restrict__ s,
                              const unsigned long long* __restrict__ d) {
    const int SAMPLES = 2048;
    const int STRIDE = (EE / 2) / SAMPLES;   // 390
    int found = 0;
    for (int j = threadIdx.x; j < SAMPLES; j += 256) {
        int w = j * STRIDE;
        if ((s[w] >> 32) | (d[w] >> 32)) found = 1;
    }
    __shared__ int sh;
    if (threadIdx.x == 0) sh = 0;
    __syncthreads();
    if (found) sh = 1;           // benign race, same value
    __syncthreads();
    if (threadIdx.x == 0) g_idx32 = sh;
}

// ---------------- K2: pre-split weights into bf16 hi/lo --------------------
__global__ void presplit_kernel(const float* __restrict__ fc_w,
                                const float* __restrict__ res_w) {
    int i = blockIdx.x * blockDim.x + threadIdx.x;
    if (i >= 32768) return;
    float v = fc_w[i];
    __nv_bfloat16 h = __float2bfloat16_rn(v);
    g_wh[i] = h;
    g_wl[i] = __float2bfloat16_rn(v - __bfloat162float(h));
    v = res_w[i];
    h = __float2bfloat16_rn(v);
    g_wh[32768 + i] = h;
    g_wl[32768 + i] = __float2bfloat16_rn(v - __bfloat162float(h));
}

// ---------------- K3: split-bf16 HMMA GEMM (+ fused el/er epilogue) -------
// C[128-tile,128] = feat[128,256] @ W^T using mma.sync m16n8k16 bf16.
// blockIdx.y == 0 -> ft (also computes el/er), == 1 -> res.
// CTA: 256 threads = 8 warps; warp grid 4(m) x 2(n); warp tile 32x64.
#define AST 40   // smem row stride in bf16 elements (80B, conflict-free ldmatrix)

__global__ __launch_bounds__(256, 1)
void gemm_mma_kernel(const float* __restrict__ feat,
                     const float* __restrict__ attn_l,
                     const float* __restrict__ attn_r) {
    __shared__ __align__(16) __nv_bfloat16 sAh[128 * AST];
    __shared__ __align__(16) __nv_bfloat16 sAl[128 * AST];
    __shared__ __align__(16) __nv_bfloat16 sBh[128 * AST];
    __shared__ __align__(16) __nv_bfloat16 sBl[128 * AST];
    __shared__ float s_attn[2 * HD];

    const int tid = threadIdx.x;
    const int wid = tid >> 5;
    const int lane = tid & 31;
    const int wm = wid & 3;          // m-warp: rows wm*32..+31
    const int wn = wid >> 2;         // n-warp: cols wn*64..+63
    const int isft = (blockIdx.y == 0);
    const int block_m = blockIdx.x * 128;
    float* __restrict__ C = isft ? g_ft : g_res;

    if (isft && tid < 128) {
        s_attn[tid] = attn_l[tid];
        s_attn[HD + tid] = attn_r[tid];
    }

    // ---- load mapping: thread pair per row; 16 consecutive k-elements ----
    const int arow = tid >> 1;               // 0..127
    const int acol0 = (tid & 1) * 16;        // 0 or 16
    const int gm = block_m + arow;
    const bool a_ok = (gm < NN);
    const float* __restrict__ Abase = feat + (size_t)(a_ok ? gm : 0) * KIN + acol0;
    const __nv_bfloat16* __restrict__ Bh_base =
        g_wh + (isft ? 0 : 32768) + arow * KIN + acol0;
    const __nv_bfloat16* __restrict__ Bl_base =
        g_wl + (isft ? 0 : 32768) + arow * KIN + acol0;

    float4 pa[4];
    uint4 pbh[2], pbl[2];
#pragma unroll
    for (int j = 0; j < 4; j++)
        pa[j] = a_ok ? *reinterpret_cast<const float4*>(Abase + j * 4)
                     : make_float4(0.f, 0.f, 0.f, 0.f);
    pbh[0] = *reinterpret_cast<const uint4*>(Bh_base);
    pbh[1] = *reinterpret_cast<const uint4*>(Bh_base + 8);
    pbl[0] = *reinterpret_cast<const uint4*>(Bl_base);
    pbl[1] = *reinterpret_cast<const uint4*>(Bl_base + 8);

    float acc[2][8][4];
#pragma unroll
    for (int mb = 0; mb < 2; mb++)
#pragma unroll
        for (int nb = 0; nb < 8; nb++)
#pragma unroll
            for (int c = 0; c < 4; c++) acc[mb][nb][c] = 0.f;

    const uint32_t sAh_b = smem_u32(sAh), sAl_b = smem_u32(sAl);
    const uint32_t sBh_b = smem_u32(sBh), sBl_b = smem_u32(sBl);
    // ldmatrix lane-address components
    const int a_row_l = (lane & 15);
    const int a_chunk = (lane >> 4);               // 0/1 -> k-halves
    const int b_kchunk = (lane >> 3) & 1;
    const int b_nhalf = (lane >> 4) & 1;           // which n8 of the pair
    const int b_row_l = (lane & 7);

#pragma unroll 1
    for (int kk = 0; kk < KIN; kk += 32) {
        // ---- write prefetched data to smem (A: hi/lo split; B: direct) ----
        {
            uint32_t h[8], l[8];
            split_pack(pa[0].x, pa[0].y, h[0], l[0]);
            split_pack(pa[0].z, pa[0].w, h[1], l[1]);
            split_pack(pa[1].x, pa[1].y, h[2], l[2]);
            split_pack(pa[1].z, pa[1].w, h[3], l[3]);
            split_pack(pa[2].x, pa[2].y, h[4], l[4]);
            split_pack(pa[2].z, pa[2].w, h[5], l[5]);
            split_pack(pa[3].x, pa[3].y, h[6], l[6]);
            split_pack(pa[3].z, pa[3].w, h[7], l[7]);
            uint4* ph = reinterpret_cast<uint4*>(&sAh[arow * AST + acol0]);
            uint4* pl = reinterpret_cast<uint4*>(&sAl[arow * AST + acol0]);
            ph[0] = make_uint4(h[0], h[1], h[2], h[3]);
            ph[1] = make_uint4(h[4], h[5], h[6], h[7]);
            pl[0] = make_uint4(l[0], l[1], l[2], l[3]);
            pl[1] = make_uint4(l[4], l[5], l[6], l[7]);

            uint4* qh = reinterpret_cast<uint4*>(&sBh[arow * AST + acol0]);
            uint4* ql = reinterpret_cast<uint4*>(&sBl[arow * AST + acol0]);
            qh[0] = pbh[0]; qh[1] = pbh[1];
            ql[0] = pbl[0]; ql[1] = pbl[1];
        }
        __syncthreads();

        // ---- prefetch next chunk (overlaps with MMA below) ----
        if (kk + 32 < KIN) {
#pragma unroll
            for (int j = 0; j < 4; j++)
                pa[j] = a_ok ? *reinterpret_cast<const float4*>(Abase + kk + 32 + j * 4)
                             : make_float4(0.f, 0.f, 0.f, 0.f);
            pbh[0] = *reinterpret_cast<const uint4*>(Bh_base + kk + 32);
            pbh[1] = *reinterpret_cast<const uint4*>(Bh_base + kk + 40);
            pbl[0] = *reinterpret_cast<const uint4*>(Bl_base + kk + 32);
            pbl[1] = *reinterpret_cast<const uint4*>(Bl_base + kk + 40);
        }

        // ---- MMA over the two k16 steps of this chunk ----
#pragma unroll
        for (int k16 = 0; k16 < 32; k16 += 16) {
            uint32_t ah[2][4], al[2][4], bh[8][2], bl[8][2];
#pragma unroll
            for (int mb = 0; mb < 2; mb++) {
                uint32_t off = (uint32_t)(((wm * 32 + mb * 16 + a_row_l) * AST +
                                           k16 + a_chunk * 8) * 2);
                ldsm_x4(ah[mb], sAh_b + off);
                ldsm_x4(al[mb], sAl_b + off);
            }
#pragma unroll
            for (int j = 0; j < 4; j++) {
                int nrow = wn * 64 + (2 * j + b_nhalf) * 8 + b_row_l;
                uint32_t off = (uint32_t)((nrow * AST + k16 + b_kchunk * 8) * 2);
                uint32_t t[4];
                ldsm_x4(t, sBh_b + off);
                bh[2 * j][0] = t[0]; bh[2 * j][1] = t[1];
                bh[2 * j + 1][0] = t[2]; bh[2 * j + 1][1] = t[3];
                ldsm_x4(t, sBl_b + off);
                bl[2 * j][0] = t[0]; bl[2 * j][1] = t[1];
                bl[2 * j + 1][0] = t[2]; bl[2 * j + 1][1] = t[3];
            }
#pragma unroll
            for (int mb = 0; mb < 2; mb++)
#pragma unroll
                for (int nb = 0; nb < 8; nb++) {
                    mma_bf16(acc[mb][nb], ah[mb], bh[nb]);
                    mma_bf16(acc[mb][nb], al[mb], bh[nb]);
                    mma_bf16(acc[mb][nb], ah[mb], bl[nb]);
                }
        }
        __syncthreads();
    }

    // ---- epilogue: store C + fused el/er (quad-shuffle reduction) ----
    const int qrow = lane >> 2;      // 0..7
    const int qcol = lane & 3;       // 0..3
#pragma unroll
    for (int mb = 0; mb < 2; mb++) {
        int r0 = block_m + wm * 32 + mb * 16 + qrow;
#pragma unroll
        for (int nb = 0; nb < 8; nb++) {
            int col = wn * 64 + nb * 8 + qcol * 2;
            if (r0 < NN)
                *reinterpret_cast<float2*>(C + (size_t)r0 * HD + col) =
                    make_float2(acc[mb][nb][0], acc[mb][nb][1]);
            if (r0 + 8 < NN)
                *reinterpret_cast<float2*>(C + (size_t)(r0 + 8) * HD + col) =
                    make_float2(acc[mb][nb][2], acc[mb][nb][3]);
        }
        if (isft) {
#pragma unroll
            for (int rr = 0; rr < 2; rr++) {
                int row = r0 + rr * 8;
#pragma unroll
                for (int hh = 0; hh < 2; hh++) {
                    float el = 0.f, er = 0.f;
#pragma unroll
                    for (int nb4 = 0; nb4 < 4; nb4++) {
                        int nb = hh * 4 + nb4;
                        int col = wn * 64 + nb * 8 + qcol * 2;
                        float v0 = acc[mb][nb][rr * 2];
                        float v1 = acc[mb][nb][rr * 2 + 1];
                        el = fmaf(v0, s_attn[col], el);
                        el = fmaf(v1, s_attn[col + 1], el);
                        er = fmaf(v0, s_attn[HD + col], er);
                        er = fmaf(v1, s_attn[HD + col + 1], er);
                    }
                    el += __shfl_xor_sync(0xffffffffu, el, 1);
                    el += __shfl_xor_sync(0xffffffffu, el, 2);
                    er += __shfl_xor_sync(0xffffffffu, er, 1);
                    er += __shfl_xor_sync(0xffffffffu, er, 2);
                    if (qcol == 0 && row < NN) {
                        int head = wn * 2 + hh;
                        g_el[row * NHEAD + head] = el;
                        g_er[row * NHEAD + head] = er;
                    }
                }
            }
        }
    }
}

// ---------------- K4: degree histogram ----------------
__global__ void hist_kernel(const void* __restrict__ dst) {
    int is32 = g_idx32;
    int i = blockIdx.x * blockDim.x + threadIdx.x;
    int stride = gridDim.x * blockDim.x;
    for (int e = i; e < EE; e += stride) {
        int d = load_idx(dst, e, is32);
        atomicAdd(&g_deg[d], 1);
    }
}

// ---------------- K5a: per-block sums for scan ----------------
__global__ void block_sums_kernel() {
    __shared__ int sh[32];
    int i = blockIdx.x * 1024 + threadIdx.x;
    int v = (i < NN) ? g_deg[i] : 0;
#pragma unroll
    for (int o = 16; o > 0; o >>= 1) v += __shfl_down_sync(0xffffffffu, v, o);
    if ((threadIdx.x & 31) == 0) sh[threadIdx.x >> 5] = v;
    __syncthreads();
    if (threadIdx.x < 32) {
        int w = sh[threadIdx.x];
#pragma unroll
        for (int o = 16; o > 0; o >>= 1) w += __shfl_down_sync(0xffffffffu, w, o);
        if (threadIdx.x == 0) g_bsum[blockIdx.x] = w;
    }
}

// ---------------- K5b: exclusive scan of block sums (tiny) ----------------
__global__ void scan_sums_kernel() {
    if (threadIdx.x == 0 && blockIdx.x == 0) {
        int running = 0;
        for (int b = 0; b < NB_SCAN; b++) {
            int t = g_bsum[b];
            g_bsum[b] = running;
            running += t;
        }
    }
}

// ---------------- K5c: per-block exclusive scan + offset ----------------
__global__ void scan_final_kernel() {
    __shared__ int sh[1024];
    int i = blockIdx.x * 1024 + threadIdx.x;
    int tid = threadIdx.x;
    int v = (i < NN) ? g_deg[i] : 0;
    int x = v;
    sh[tid] = x;
    __syncthreads();
#pragma unroll
    for (int off = 1; off < 1024; off <<= 1) {
        int y = (tid >= off) ? sh[tid - off] : 0;
        __syncthreads();
        x += y;
        sh[tid] = x;
        __syncthreads();
    }
    if (i < NN) {
        int excl = x - v + g_bsum[blockIdx.x];
        g_rowptr[i] = excl;
        g_fill[i] = excl;
    }
}

// ---------------- K6: scatter edges into CSR (by dst) ----------------
__global__ void scatter_kernel(const void* __restrict__ src,
                               const void* __restrict__ dst) {
    int is32 = g_idx32;
    int i = blockIdx.x * blockDim.x + threadIdx.x;
    int stride = gridDim.x * blockDim.x;
    for (int e = i; e < EE; e += stride) {
        int d = load_idx(dst, e, is32);
        int s = load_idx(src, e, is32);
        int pos = atomicAdd(&g_fill[d], 1);
        g_esrc[pos] = s;
    }
}

// ---------------- K7: fused edge-softmax + aggregation + residual ----------
// One warp per node, all 4 heads (lane = d), edge loop unrolled x2 with
// independent accumulator sets for 2x memory-level parallelism.
__global__ __launch_bounds__(256)
void agg_kernel(float* __restrict__ out, int out_size) {
    int n = (blockIdx.x * blockDim.x + threadIdx.x) >> 5;
    int lane = threadIdx.x & 31;
    if (n >= NN) return;

    int start = g_rowptr[n];
    int len = g_deg[n];
    const float4 ern = *reinterpret_cast<const float4*>(&g_er[n * NHEAD]);
    const float4* __restrict__ el4 = reinterpret_cast<const float4*>(g_el);
    const int* __restrict__ esrc = g_esrc + start;

    float a0 = 0.f, a1 = 0.f, a2 = 0.f, a3 = 0.f;
    float s0 = 0.f, s1 = 0.f, s2 = 0.f, s3 = 0.f;
    float b0 = 0.f, b1 = 0.f, b2 = 0.f, b3 = 0.f;
    float t0 = 0.f, t1 = 0.f, t2 = 0.f, t3 = 0.f;

    int i = 0;
    for (; i + 2 <= len; i += 2) {
        int sa = esrc[i];
        int sb = esrc[i + 1];
        float4 ea = el4[sa];
        float4 eb = el4[sb];
        const float* __restrict__ fa = g_ft + (size_t)sa * HD + lane;
        const float* __restrict__ fb = g_ft + (size_t)sb * HD + lane;
        float fa0 = fa[0], fa1 = fa[32], fa2 = fa[64], fa3 = fa[96];
        float fb0 = fb[0], fb1 = fb[32], fb2 = fb[64], fb3 = fb[96];

        float e;
        e = ea.x + ern.x; e = (e > 0.f) ? e : NEG_SLOPE * e; float xa0 = __expf(e);
        e = ea.y + ern.y; e = (e > 0.f) ? e : NEG_SLOPE * e; float xa1 = __expf(e);
        e = ea.z + ern.z; e = (e > 0.f) ? e : NEG_SLOPE * e; float xa2 = __expf(e);
        e = ea.w + ern.w; e = (e > 0.f) ? e : NEG_SLOPE * e; float xa3 = __expf(e);
        e = eb.x + ern.x; e = (e > 0.f) ? e : NEG_SLOPE * e; float xb0 = __expf(e);
        e = eb.y + ern.y; e = (e > 0.f) ? e : NEG_SLOPE * e; float xb1 = __expf(e);
        e = eb.z + ern.z; e = (e > 0.f) ? e : NEG_SLOPE * e; float xb2 = __expf(e);
        e = eb.w + ern.w; e = (e > 0.f) ? e : NEG_SLOPE * e; float xb3 = __expf(e);

        s0 += xa0; s1 += xa1; s2 += xa2; s3 += xa3;
        t0 += xb0; t1 += xb1; t2 += xb2; t3 += xb3;
        a0 = fmaf(xa0, fa0, a0); a1 = fmaf(xa1, fa1, a1);
        a2 = fmaf(xa2, fa2, a2); a3 = fmaf(xa3, fa3, a3);
        b0 = fmaf(xb0, fb0, b0); b1 = fmaf(xb1, fb1, b1);
        b2 = fmaf(xb2, fb2, b2); b3 = fmaf(xb3, fb3, b3);
    }
    if (i < len) {
        int sa = esrc[i];
        float4 ea = el4[sa];
        const float* __restrict__ fa = g_ft + (size_t)sa * HD + lane;
        float e;
        e = ea.x + ern.x; e = (e > 0.f) ? e : NEG_SLOPE * e; float x0 = __expf(e);
        e = ea.y + ern.y; e = (e > 0.f) ? e : NEG_SLOPE * e; float x1 = __expf(e);
        e = ea.z + ern.z; e = (e > 0.f) ? e : NEG_SLOPE * e; float x2 = __expf(e);
        e = ea.w + ern.w; e = (e > 0.f) ? e : NEG_SLOPE * e; float x3 = __expf(e);
        s0 += x0; s1 += x1; s2 += x2; s3 += x3;
        a0 = fmaf(x0, fa[0],  a0); a1 = fmaf(x1, fa[32], a1);
        a2 = fmaf(x2, fa[64], a2); a3 = fmaf(x3, fa[96], a3);
    }
    s0 += t0; s1 += t1; s2 += t2; s3 += t3;
    a0 += b0; a1 += b1; a2 += b2; a3 += b3;

    float r0 = len ? a0 / s0 : 0.f;
    float r1 = len ? a1 / s1 : 0.f;
    float r2 = len ? a2 / s2 : 0.f;
    float r3 = len ? a3 / s3 : 0.f;

    size_t o = (size_t)n * HD + lane;
    out[o]      = r0 + g_res[o];
    out[o + 32] = r1 + g_res[o + 32];
    out[o + 64] = r2 + g_res[o + 64];
    out[o + 96] = r3 + g_res[o + 96];
    if (out_size >= 2 * NN * HD) {
        size_t o2 = (size_t)NN * HD + o;
        out[o2]      = r0;
        out[o2 + 32] = r1;
        out[o2 + 64] = r2;
        out[o2 + 96] = r3;
    }
}

// ---------------- launch ----------------
extern "C" void kernel_launch(void* const* d_in, const int* in_sizes, int n_in,
                              void* d_out, int out_size) {
    const float* feat   = (const float*)d_in[0];
    const void*  src    = d_in[1];
    const void*  dst    = d_in[2];
    const float* fc_w   = (const float*)d_in[3];
    const float* attn_l = (const float*)d_in[4];
    const float* attn_r = (const float*)d_in[5];
    const float* res_w  = (const float*)d_in[6];
    float* out = (float*)d_out;

    zero_kernel<<<(NN + 255) / 256, 256>>>();
    detect_kernel<<<1, 256>>>((const unsigned long long*)src,
                              (const unsigned long long*)dst);
    presplit_kernel<<<128, 256>>>(fc_w, res_w);

    dim3 ggrid((NN + 127) / 128, 2);
    gemm_mma_kernel<<<ggrid, 256>>>(feat, attn_l, attn_r);

    hist_kernel<<<2048, 256>>>(dst);
    block_sums_kernel<<<NB_SCAN, 1024>>>();
    scan_sums_kernel<<<1, 32>>>();
    scan_final_kernel<<<NB_SCAN, 1024>>>();
    scatter_kernel<<<2048, 256>>>(src, dst);

    int blocks = (NN * 32 + 255) / 256;   // one warp per node
    agg_kernel<<<blocks, 256>>>(out, out_size);
}